// round 1
// baseline (speedup 1.0000x reference)
#include <cuda_runtime.h>
#include <math.h>

#define D     1024
#define BATCH 4
#define NSEQ  2048
#define MROWS (BATCH*NSEQ)   // 8192

// ---------------- scratch (static device allocations; no cudaMalloc) ----------------
__device__ float g_Wm[D*D];       // Wq @ Wk^T            (4 MB)
__device__ float g_T [MROWS*D];   // x @ Wm               (32 MB)
__device__ float g_w1[D];         // Wq @ bk
__device__ float g_w2[D];         // Wk @ bq
__device__ float g_s [MROWS];     // x @ Wo + bo
__device__ float g_p [MROWS];     // x @ w1
__device__ float g_q [MROWS];     // x @ w2
__device__ float g_c0;            // bq . bk

// ---------------- small vector kernels ----------------
__global__ void vecs_kernel(const float* __restrict__ Wq, const float* __restrict__ Wk,
                            const float* __restrict__ bq, const float* __restrict__ bk) {
    int gw   = (blockIdx.x * blockDim.x + threadIdx.x) >> 5;
    int lane = threadIdx.x & 31;
    float acc = 0.f;
    if (gw < D) {
        const float* row = Wq + (size_t)gw * D;
        for (int k = lane; k < D; k += 32) acc += row[k] * bk[k];
        #pragma unroll
        for (int o = 16; o > 0; o >>= 1) acc += __shfl_down_sync(0xffffffffu, acc, o);
        if (lane == 0) g_w1[gw] = acc;
    } else if (gw < 2*D) {
        const float* row = Wk + (size_t)(gw - D) * D;
        for (int k = lane; k < D; k += 32) acc += row[k] * bq[k];
        #pragma unroll
        for (int o = 16; o > 0; o >>= 1) acc += __shfl_down_sync(0xffffffffu, acc, o);
        if (lane == 0) g_w2[gw - D] = acc;
    } else if (gw == 2*D) {
        for (int k = lane; k < D; k += 32) acc += bq[k] * bk[k];
        #pragma unroll
        for (int o = 16; o > 0; o >>= 1) acc += __shfl_down_sync(0xffffffffu, acc, o);
        if (lane == 0) g_c0 = acc;
    }
}

// one warp per row: s, p, q in a single pass over x
__global__ void rows_kernel(const float* __restrict__ x, const float* __restrict__ Wo,
                            const float* __restrict__ bo) {
    int gw   = (blockIdx.x * blockDim.x + threadIdx.x) >> 5;
    int lane = threadIdx.x & 31;
    if (gw >= MROWS) return;
    const float* row = x + (size_t)gw * D;
    float ss = 0.f, pp = 0.f, qq = 0.f;
    for (int k = lane; k < D; k += 32) {
        float xv = row[k];
        ss += xv * Wo[k];
        pp += xv * g_w1[k];
        qq += xv * g_w2[k];
    }
    #pragma unroll
    for (int o = 16; o > 0; o >>= 1) {
        ss += __shfl_down_sync(0xffffffffu, ss, o);
        pp += __shfl_down_sync(0xffffffffu, pp, o);
        qq += __shfl_down_sync(0xffffffffu, qq, o);
    }
    if (lane == 0) { g_s[gw] = ss + bo[0]; g_p[gw] = pp; g_q[gw] = qq; }
}

// ---------------- SGEMM tile helpers (BM=BN=128, BK=16, 256 threads, 8x8/thread) ----

// load 128 rows x 16 k-cols of a row-major [rows x D] matrix, transposed into sm[k][row]
__device__ __forceinline__ void load_trans_tile(const float* __restrict__ base, int k0,
                                                float sm[16][128], int tid) {
    #pragma unroll
    for (int it = 0; it < 2; it++) {
        int idx = tid + it * 256;
        int r   = idx >> 2;
        int c4  = (idx & 3) * 4;
        float4 v = *(const float4*)(base + (size_t)r * D + k0 + c4);
        sm[c4+0][r] = v.x; sm[c4+1][r] = v.y; sm[c4+2][r] = v.z; sm[c4+3][r] = v.w;
    }
}

// load 16 k-rows x 128 cols of a row-major [D x cols(=D)] matrix directly into sm[k][col]
__device__ __forceinline__ void load_direct_tile(const float* __restrict__ base, int k0,
                                                 float sm[16][128], int tid) {
    #pragma unroll
    for (int it = 0; it < 2; it++) {
        int idx = tid + it * 256;
        int r   = idx >> 5;
        int c4  = (idx & 31) * 4;
        float4 v = *(const float4*)(base + (size_t)(k0 + r) * D + c4);
        *(float4*)(&sm[r][c4]) = v;
    }
}

__device__ __forceinline__ void mma_tile(const float As[16][128], const float Bs[16][128],
                                         float acc[8][8], int tx, int ty) {
    #pragma unroll
    for (int k = 0; k < 16; k++) {
        __align__(16) float a[8], b[8];
        *(float4*)(a)   = *(const float4*)(&As[k][ty*8]);
        *(float4*)(a+4) = *(const float4*)(&As[k][ty*8+4]);
        *(float4*)(b)   = *(const float4*)(&Bs[k][tx*8]);
        *(float4*)(b+4) = *(const float4*)(&Bs[k][tx*8+4]);
        #pragma unroll
        for (int i = 0; i < 8; i++)
            #pragma unroll
            for (int j = 0; j < 8; j++)
                acc[i][j] += a[i] * b[j];
    }
}

// ---------------- Wm = Wq @ Wk^T  (NT, 1024x1024x1024) ----------------
__global__ __launch_bounds__(256) void gemm_nt_wm(const float* __restrict__ A,
                                                  const float* __restrict__ B) {
    __shared__ float As[16][128];
    __shared__ float Bs[16][128];
    int tid = threadIdx.x, tx = tid & 15, ty = tid >> 4;
    const float* Ab = A + (size_t)(blockIdx.y * 128) * D;
    const float* Bb = B + (size_t)(blockIdx.x * 128) * D;
    float acc[8][8] = {};
    for (int k0 = 0; k0 < D; k0 += 16) {
        load_trans_tile(Ab, k0, As, tid);
        load_trans_tile(Bb, k0, Bs, tid);
        __syncthreads();
        mma_tile(As, Bs, acc, tx, ty);
        __syncthreads();
    }
    #pragma unroll
    for (int i = 0; i < 8; i++) {
        int row = blockIdx.y * 128 + ty * 8 + i;
        float4* dst = (float4*)(g_Wm + (size_t)row * D + blockIdx.x * 128 + tx * 8);
        dst[0] = make_float4(acc[i][0], acc[i][1], acc[i][2], acc[i][3]);
        dst[1] = make_float4(acc[i][4], acc[i][5], acc[i][6], acc[i][7]);
    }
}

// ---------------- T = x @ Wm  (NN, 8192x1024x1024) ----------------
__global__ __launch_bounds__(256) void gemm_nn_T(const float* __restrict__ x) {
    __shared__ float As[16][128];
    __shared__ float Bs[16][128];
    int tid = threadIdx.x, tx = tid & 15, ty = tid >> 4;
    const float* Ab = x + (size_t)(blockIdx.y * 128) * D;
    const float* Bb = g_Wm + blockIdx.x * 128;
    float acc[8][8] = {};
    for (int k0 = 0; k0 < D; k0 += 16) {
        load_trans_tile(Ab, k0, As, tid);
        load_direct_tile(Bb, k0, Bs, tid);
        __syncthreads();
        mma_tile(As, Bs, acc, tx, ty);
        __syncthreads();
    }
    #pragma unroll
    for (int i = 0; i < 8; i++) {
        int row = blockIdx.y * 128 + ty * 8 + i;
        float4* dst = (float4*)(g_T + (size_t)row * D + blockIdx.x * 128 + tx * 8);
        dst[0] = make_float4(acc[i][0], acc[i][1], acc[i][2], acc[i][3]);
        dst[1] = make_float4(acc[i][4], acc[i][5], acc[i][6], acc[i][7]);
    }
}

// ---------------- out[b] = scale*(T_b @ x_b^T + p_i + q_j + c0) + 5*tanh(s_j - s_i) ---
__global__ __launch_bounds__(256) void gemm_epi(const float* __restrict__ x,
                                                float* __restrict__ out) {
    __shared__ float As[16][128];
    __shared__ float Bs[16][128];
    int tid = threadIdx.x, tx = tid & 15, ty = tid >> 4;
    int b = blockIdx.z;
    const float* Ab = g_T + ((size_t)b * NSEQ + blockIdx.y * 128) * D;
    const float* Bb = x   + ((size_t)b * NSEQ + blockIdx.x * 128) * D;
    float acc[8][8] = {};
    for (int k0 = 0; k0 < D; k0 += 16) {
        load_trans_tile(Ab, k0, As, tid);
        load_trans_tile(Bb, k0, Bs, tid);
        __syncthreads();
        mma_tile(As, Bs, acc, tx, ty);
        __syncthreads();
    }
    const float scale = 0.03125f; // 1024^-0.5
    int mbase = b * NSEQ + blockIdx.y * 128 + ty * 8;
    int nbase = b * NSEQ + blockIdx.x * 128 + tx * 8;
    float pi[8], si[8], qj[8], sj[8];
    #pragma unroll
    for (int i = 0; i < 8; i++) { pi[i] = g_p[mbase + i]; si[i] = g_s[mbase + i]; }
    #pragma unroll
    for (int j = 0; j < 8; j++) { qj[j] = g_q[nbase + j]; sj[j] = g_s[nbase + j]; }
    float c0 = g_c0;
    size_t obase = (size_t)b * NSEQ * NSEQ + (size_t)(blockIdx.y * 128 + ty * 8) * NSEQ
                 + blockIdx.x * 128 + tx * 8;
    #pragma unroll
    for (int i = 0; i < 8; i++) {
        float v[8];
        #pragma unroll
        for (int j = 0; j < 8; j++)
            v[j] = scale * (acc[i][j] + pi[i] + qj[j] + c0) + 5.f * tanhf(sj[j] - si[i]);
        float4* dst = (float4*)(out + obase + (size_t)i * NSEQ);
        dst[0] = make_float4(v[0], v[1], v[2], v[3]);
        dst[1] = make_float4(v[4], v[5], v[6], v[7]);
    }
}

// ---------------- launch ----------------
extern "C" void kernel_launch(void* const* d_in, const int* in_sizes, int n_in,
                              void* d_out, int out_size) {
    const float* x  = (const float*)d_in[0];
    const float* Wq = (const float*)d_in[1];
    const float* bq = (const float*)d_in[2];
    const float* Wk = (const float*)d_in[3];
    const float* bk = (const float*)d_in[4];
    const float* Wo = (const float*)d_in[5];
    const float* bo = (const float*)d_in[6];
    float* out = (float*)d_out;

    // w1, w2, c0  (2049 warps)
    vecs_kernel<<<257, 256>>>(Wq, Wk, bq, bk);
    // s, p, q  (depends on w1/w2; 8192 warps)
    rows_kernel<<<1024, 256>>>(x, Wo, bo);
    // Wm = Wq @ Wk^T
    gemm_nt_wm<<<dim3(8, 8), 256>>>(Wq, Wk);
    // T = x @ Wm
    gemm_nn_T<<<dim3(8, 64), 256>>>(x);
    // final logits + ordering bias
    gemm_epi<<<dim3(16, 16, BATCH), 256>>>(x, out);
}

// round 3
// speedup vs baseline: 2.1285x; 2.1285x over previous
#include <cuda_runtime.h>
#include <cstdint>
#include <math.h>

#define D      1024
#define BATCH  4
#define NSEQ   2048
#define MROWS  (BATCH*NSEQ)

#define BM     256
#define BN     128
#define BK     16
#define NITER  (D/BK)        // 64
#define THREADS 256

// fragment-packed smem tile sizes (words)
#define AS_WORDS ((BK/8)*(BM/16)*128)   // 4096 = 16KB
#define BS_WORDS ((BK/8)*(BN/8)*64)     // 2048 = 8KB

// ---------------- scratch ----------------
__device__ float g_Wm[D*D];       // Wm'[n,k] = Wm[k,n] = (Wk @ Wq^T)[n,k]
__device__ float g_T [MROWS*D];   // x @ Wm
__device__ float g_w1[D];         // Wq @ bk
__device__ float g_w2[D];         // Wk @ bq
__device__ float g_P [MROWS];     // scale*(x@w1 + c0)   (row term)
__device__ float g_Q [MROWS];     // scale*(x@w2)        (col term)
__device__ float g_u [MROWS];     // tanh(x@Wo + bo)
__device__ float g_c0;            // bq . bk

__device__ __forceinline__ uint32_t tf32r(float x) {
    uint32_t o; asm("cvt.rna.tf32.f32 %0, %1;" : "=r"(o) : "f"(x));
    return o;
}

__device__ __forceinline__ void mma_tf32(float c[4], const uint32_t a[4], const uint32_t b[2]) {
    asm volatile(
        "mma.sync.aligned.m16n8k8.row.col.f32.tf32.tf32.f32 "
        "{%0,%1,%2,%3}, {%4,%5,%6,%7}, {%8,%9}, {%0,%1,%2,%3};"
        : "+f"(c[0]), "+f"(c[1]), "+f"(c[2]), "+f"(c[3])
        : "r"(a[0]), "r"(a[1]), "r"(a[2]), "r"(a[3]), "r"(b[0]), "r"(b[1]));
}

// fragment-order word index for A element (m in 0..BM-1, k in 0..BK-1)
__device__ __forceinline__ int a_word(int m, int k) {
    int blk = (k >> 3) * (BM/16) + (m >> 4);
    return blk * 128 + ((m & 7) * 4 + (k & 3)) * 4 + ((k >> 2) & 1) * 2 + ((m >> 3) & 1);
}
// fragment-order word index for B element (n in 0..BN-1, k in 0..BK-1)
__device__ __forceinline__ int b_word(int n, int k) {
    int blk = (k >> 3) * (BN/8) + (n >> 3);
    return blk * 64 + ((n & 7) * 4 + (k & 3)) * 2 + ((k >> 2) & 1);
}

// ---------------- small vector kernels ----------------
__global__ void vecs_kernel(const float* __restrict__ Wq, const float* __restrict__ Wk,
                            const float* __restrict__ bq, const float* __restrict__ bk) {
    int gw   = (blockIdx.x * blockDim.x + threadIdx.x) >> 5;
    int lane = threadIdx.x & 31;
    float acc = 0.f;
    if (gw < D) {
        const float* row = Wq + (size_t)gw * D;
        for (int k = lane; k < D; k += 32) acc += row[k] * bk[k];
        #pragma unroll
        for (int o = 16; o > 0; o >>= 1) acc += __shfl_down_sync(0xffffffffu, acc, o);
        if (lane == 0) g_w1[gw] = acc;
    } else if (gw < 2*D) {
        const float* row = Wk + (size_t)(gw - D) * D;
        for (int k = lane; k < D; k += 32) acc += row[k] * bq[k];
        #pragma unroll
        for (int o = 16; o > 0; o >>= 1) acc += __shfl_down_sync(0xffffffffu, acc, o);
        if (lane == 0) g_w2[gw - D] = acc;
    } else if (gw == 2*D) {
        for (int k = lane; k < D; k += 32) acc += bq[k] * bk[k];
        #pragma unroll
        for (int o = 16; o > 0; o >>= 1) acc += __shfl_down_sync(0xffffffffu, acc, o);
        if (lane == 0) g_c0 = acc;
    }
}

__global__ void rows_kernel(const float* __restrict__ x, const float* __restrict__ Wo,
                            const float* __restrict__ bo) {
    int gw   = (blockIdx.x * blockDim.x + threadIdx.x) >> 5;
    int lane = threadIdx.x & 31;
    if (gw >= MROWS) return;
    const float* row = x + (size_t)gw * D;
    float ss = 0.f, pp = 0.f, qq = 0.f;
    for (int k = lane; k < D; k += 32) {
        float xv = row[k];
        ss += xv * Wo[k];
        pp += xv * g_w1[k];
        qq += xv * g_w2[k];
    }
    #pragma unroll
    for (int o = 16; o > 0; o >>= 1) {
        ss += __shfl_down_sync(0xffffffffu, ss, o);
        pp += __shfl_down_sync(0xffffffffu, pp, o);
        qq += __shfl_down_sync(0xffffffffu, qq, o);
    }
    if (lane == 0) {
        const float scale = 0.03125f;
        g_u[gw] = tanhf(ss + bo[0]);
        g_P[gw] = scale * (pp + g_c0);
        g_Q[gw] = scale * qq;
    }
}

// ---------------- tf32 mma.sync GEMM: C[m,n] = sum_k A[m,k]*B[n,k] ----------------
// MODE 0: plain store.  MODE 1: fused epilogue, batched over blockIdx.z.
template<int MODE>
__global__ void __launch_bounds__(THREADS, 1) mm_kernel(
    const float* __restrict__ A, const float* __restrict__ B,
    float* __restrict__ C, int ldc)
{
    __shared__ __align__(16) uint32_t As[2][AS_WORDS];
    __shared__ __align__(16) uint32_t Bs[2][BS_WORDS];

    const int tid  = threadIdx.x;
    const int w    = tid >> 5;
    const int lane = tid & 31;
    const int wm   = (w >> 1) * 64;     // warp row offset in tile
    const int wn   = (w & 1) * 64;      // warp col offset in tile

    const int m0 = blockIdx.y * BM;
    const int n0 = blockIdx.x * BN;

    const float* Ab;
    const float* Bb;
    if (MODE == 1) {
        size_t zo = (size_t)blockIdx.z * NSEQ * D;
        Ab = A + zo + (size_t)m0 * D;
        Bb = B + zo + (size_t)n0 * D;
    } else {
        Ab = A + (size_t)m0 * D;
        Bb = B + (size_t)n0 * D;
    }

    float acc[4][8][4];
    #pragma unroll
    for (int i = 0; i < 4; i++)
        #pragma unroll
        for (int j = 0; j < 8; j++)
            #pragma unroll
            for (int e = 0; e < 4; e++) acc[i][j][e] = 0.f;

    float4 ra[4], rb[2];

    // ---- prologue: load + stage tile 0 ----
    #pragma unroll
    for (int t = 0; t < 4; t++) {
        int idx = tid + t * THREADS;             // 0..1023
        int r = idx >> 2, c4 = idx & 3;
        ra[t] = *(const float4*)(Ab + (size_t)r * D + c4 * 4);
    }
    #pragma unroll
    for (int t = 0; t < 2; t++) {
        int idx = tid + t * THREADS;             // 0..511
        int r = idx >> 2, c4 = idx & 3;
        rb[t] = *(const float4*)(Bb + (size_t)r * D + c4 * 4);
    }
    #pragma unroll
    for (int t = 0; t < 4; t++) {
        int idx = tid + t * THREADS;
        int r = idx >> 2, c4 = idx & 3;
        const float* v = (const float*)&ra[t];
        #pragma unroll
        for (int e = 0; e < 4; e++) As[0][a_word(r, c4 * 4 + e)] = tf32r(v[e]);
    }
    #pragma unroll
    for (int t = 0; t < 2; t++) {
        int idx = tid + t * THREADS;
        int r = idx >> 2, c4 = idx & 3;
        const float* v = (const float*)&rb[t];
        #pragma unroll
        for (int e = 0; e < 4; e++) Bs[0][b_word(r, c4 * 4 + e)] = tf32r(v[e]);
    }
    __syncthreads();

    const int mblk0 = wm >> 4;   // 0 or 4... (w>>1)*4
    const int nblk0 = wn >> 3;   // (w&1)*8

    for (int it = 0; it < NITER; it++) {
        int buf = it & 1;
        // prefetch next tile into registers
        if (it + 1 < NITER) {
            int k0 = (it + 1) * BK;
            #pragma unroll
            for (int t = 0; t < 4; t++) {
                int idx = tid + t * THREADS;
                int r = idx >> 2, c4 = idx & 3;
                ra[t] = *(const float4*)(Ab + (size_t)r * D + k0 + c4 * 4);
            }
            #pragma unroll
            for (int t = 0; t < 2; t++) {
                int idx = tid + t * THREADS;
                int r = idx >> 2, c4 = idx & 3;
                rb[t] = *(const float4*)(Bb + (size_t)r * D + k0 + c4 * 4);
            }
        }
        // compute on current buffer
        #pragma unroll
        for (int ks = 0; ks < BK/8; ks++) {
            uint32_t afr[4][4];
            uint32_t bfr[8][2];
            #pragma unroll
            for (int tm = 0; tm < 4; tm++) {
                int blk = ks * (BM/16) + mblk0 + tm;
                *(uint4*)afr[tm] = *(const uint4*)&As[buf][blk * 128 + lane * 4];
            }
            #pragma unroll
            for (int tn = 0; tn < 8; tn++) {
                int blk = ks * (BN/8) + nblk0 + tn;
                *(uint2*)bfr[tn] = *(const uint2*)&Bs[buf][blk * 64 + lane * 2];
            }
            #pragma unroll
            for (int tm = 0; tm < 4; tm++)
                #pragma unroll
                for (int tn = 0; tn < 8; tn++)
                    mma_tf32(acc[tm][tn], afr[tm], bfr[tn]);
        }
        // stage next tile into the other buffer
        if (it + 1 < NITER) {
            int nb = buf ^ 1;
            #pragma unroll
            for (int t = 0; t < 4; t++) {
                int idx = tid + t * THREADS;
                int r = idx >> 2, c4 = idx & 3;
                const float* v = (const float*)&ra[t];
                #pragma unroll
                for (int e = 0; e < 4; e++) As[nb][a_word(r, c4 * 4 + e)] = tf32r(v[e]);
            }
            #pragma unroll
            for (int t = 0; t < 2; t++) {
                int idx = tid + t * THREADS;
                int r = idx >> 2, c4 = idx & 3;
                const float* v = (const float*)&rb[t];
                #pragma unroll
                for (int e = 0; e < 4; e++) Bs[nb][b_word(r, c4 * 4 + e)] = tf32r(v[e]);
            }
        }
        __syncthreads();
    }

    // ---- epilogue ----
    if (MODE == 0) {
        #pragma unroll
        for (int tm = 0; tm < 4; tm++) {
            int row0 = m0 + wm + tm * 16 + (lane >> 2);
            #pragma unroll
            for (int tn = 0; tn < 8; tn++) {
                int col = n0 + wn + tn * 8 + (lane & 3) * 2;
                float2* p0 = (float2*)(C + (size_t)row0 * ldc + col);
                float2* p1 = (float2*)(C + (size_t)(row0 + 8) * ldc + col);
                *p0 = make_float2(acc[tm][tn][0], acc[tm][tn][1]);
                *p1 = make_float2(acc[tm][tn][2], acc[tm][tn][3]);
            }
        }
    } else {
        // stage col terms for this tile's BN columns
        float* sQ = (float*)As[0];
        float* sU = sQ + BN;
        int jg0 = blockIdx.z * NSEQ + n0;
        if (tid < BN) { sQ[tid] = g_Q[jg0 + tid]; sU[tid] = g_u[jg0 + tid]; }
        __syncthreads();

        const float scale = 0.03125f;
        size_t zrow = (size_t)blockIdx.z * NSEQ;
        #pragma unroll
        for (int tm = 0; tm < 4; tm++) {
            int rloc0 = m0 + wm + tm * 16 + (lane >> 2);
            int rg0 = (int)zrow + rloc0;
            float P0 = g_P[rg0],     u0 = g_u[rg0];
            float P1 = g_P[rg0 + 8], u1 = g_u[rg0 + 8];
            float* c0p = C + (zrow + rloc0) * (size_t)ldc + n0;
            float* c1p = C + (zrow + rloc0 + 8) * (size_t)ldc + n0;
            #pragma unroll
            for (int tn = 0; tn < 8; tn++) {
                int jl = wn + tn * 8 + (lane & 3) * 2;
                float qa = sQ[jl],   ua = sU[jl];
                float qb = sQ[jl+1], ub = sU[jl+1];
                float v00 = fmaf(scale, acc[tm][tn][0], P0 + qa)
                          + 5.f * __fdividef(ua - u0, fmaf(-u0, ua, 1.f));
                float v01 = fmaf(scale, acc[tm][tn][1], P0 + qb)
                          + 5.f * __fdividef(ub - u0, fmaf(-u0, ub, 1.f));
                float v10 = fmaf(scale, acc[tm][tn][2], P1 + qa)
                          + 5.f * __fdividef(ua - u1, fmaf(-u1, ua, 1.f));
                float v11 = fmaf(scale, acc[tm][tn][3], P1 + qb)
                          + 5.f * __fdividef(ub - u1, fmaf(-u1, ub, 1.f));
                *(float2*)(c0p + jl) = make_float2(v00, v01);
                *(float2*)(c1p + jl) = make_float2(v10, v11);
            }
        }
    }
}

// ---------------- launch ----------------
extern "C" void kernel_launch(void* const* d_in, const int* in_sizes, int n_in,
                              void* d_out, int out_size) {
    const float* x  = (const float*)d_in[0];
    const float* Wq = (const float*)d_in[1];
    const float* bq = (const float*)d_in[2];
    const float* Wk = (const float*)d_in[3];
    const float* bk = (const float*)d_in[4];
    const float* Wo = (const float*)d_in[5];
    const float* bo = (const float*)d_in[6];
    float* out = (float*)d_out;

    float *pWm, *pT;
    cudaGetSymbolAddress((void**)&pWm, g_Wm);
    cudaGetSymbolAddress((void**)&pT,  g_T);

    // bias precompute
    vecs_kernel<<<257, 256>>>(Wq, Wk, bq, bk);
    rows_kernel<<<1024, 256>>>(x, Wo, bo);
    // Wm'[n,k] = Wm[k,n]:  Wm' = Wk @ Wq^T
    mm_kernel<0><<<dim3(D/BN, D/BM), THREADS>>>(Wk, Wq, pWm, D);
    // T = x @ Wm  via  T[m,n] = x[m,:] . Wm'[n,:]
    mm_kernel<0><<<dim3(D/BN, MROWS/BM), THREADS>>>(x, pWm, pT, D);
    // out[b,i,j] = scale*(T_b[i,:].x_b[j,:]) + P_i + Q_j + 5*tanh-identity
    mm_kernel<1><<<dim3(NSEQ/BN, NSEQ/BM, BATCH), THREADS>>>(pT, x, out, NSEQ);
}

// round 4
// speedup vs baseline: 3.4760x; 1.6330x over previous
#include <cuda_runtime.h>
#include <cstdint>
#include <math.h>

#define D      1024
#define BATCH  4
#define NSEQ   2048
#define MROWS  (BATCH*NSEQ)
#define BN     128
#define BK     16
#define NITER  (D/BK)        // 64
#define THREADS 256

// ---------------- scratch (packed tf32 fragment-order operands) ----------------
__device__ uint32_t g_xA [MROWS*D];   // x packed as A-operand   (32MB)
__device__ uint32_t g_xB [MROWS*D];   // x packed as B-operand   (32MB)
__device__ uint32_t g_WkA[D*D];       // Wk packed as A          (4MB)
__device__ uint32_t g_WqB[D*D];       // Wq packed as B          (4MB)
__device__ uint32_t g_WmB[D*D];       // Wm' packed as B         (4MB)
__device__ uint32_t g_TA [MROWS*D];   // T packed as A           (32MB)
__device__ float g_w1[D];             // Wq @ bk
__device__ float g_w2[D];             // Wk @ bq
__device__ float g_P [MROWS];         // scale*(x@w1 + c0)
__device__ float g_Q [MROWS];         // scale*(x@w2)
__device__ float g_u [MROWS];         // tanh(x@Wo + bo)
__device__ float g_c0;                // bq . bk

__device__ __forceinline__ uint32_t tf32r(float x) {
    uint32_t o; asm("cvt.rna.tf32.f32 %0, %1;" : "=r"(o) : "f"(x));
    return o;
}
__device__ __forceinline__ void cp16(uint32_t saddr, const void* g) {
    asm volatile("cp.async.cg.shared.global [%0], [%1], 16;" :: "r"(saddr), "l"(g) : "memory");
}
__device__ __forceinline__ void mma_tf32(float c[4], const uint32_t a[4], const uint32_t b[2]) {
    asm volatile(
        "mma.sync.aligned.m16n8k8.row.col.f32.tf32.tf32.f32 "
        "{%0,%1,%2,%3}, {%4,%5,%6,%7}, {%8,%9}, {%0,%1,%2,%3};"
        : "+f"(c[0]), "+f"(c[1]), "+f"(c[2]), "+f"(c[3])
        : "r"(a[0]), "r"(a[1]), "r"(a[2]), "r"(a[3]), "r"(b[0]), "r"(b[1]));
}

// ---------------- pack kernels: row-major fp32 -> fragment-order tf32 ----------------
// A layout: word = (k>>3)*(R/16)*128 + (m>>4)*128 + ((m&7)*4+(k&3))*4 + ((k>>2)&1)*2 + ((m>>3)&1)
// B layout: word = (k>>3)*(R/8)*64   + (n>>3)*64  + ((n&7)*4+(k&3))*2 + ((k>>2)&1)
__global__ void pack_A(const float* __restrict__ src, uint32_t* __restrict__ dst, int R) {
    __shared__ float s[128][36];
    int tid = threadIdx.x;
    int r0 = blockIdx.x * 128, c0 = blockIdx.y * 32;
    #pragma unroll
    for (int j = 0; j < 4; j++) {
        int idx = tid + j * 256;
        int r = idx >> 3, c4 = (idx & 7) * 4;
        *(float4*)&s[r][c4] = *(const float4*)(src + (size_t)(r0 + r) * D + c0 + c4);
    }
    __syncthreads();
    int w = tid >> 5, l = tid & 31;
    #pragma unroll
    for (int jj = 0; jj < 4; jj++) {
        int bi = w + jj * 8;          // 0..31
        int mb = bi & 7, kb = bi >> 3;
        int mr = mb * 16 + (l >> 2), kc = kb * 8 + (l & 3);
        uint4 v;
        v.x = tf32r(s[mr][kc]);
        v.y = tf32r(s[mr + 8][kc]);
        v.z = tf32r(s[mr][kc + 4]);
        v.w = tf32r(s[mr + 8][kc + 4]);
        size_t blk = (size_t)((c0 >> 3) + kb) * (R / 16) + (r0 >> 4) + mb;
        *(uint4*)(dst + blk * 128 + l * 4) = v;
    }
}
__global__ void pack_B(const float* __restrict__ src, uint32_t* __restrict__ dst, int R) {
    __shared__ float s[128][36];
    int tid = threadIdx.x;
    int r0 = blockIdx.x * 128, c0 = blockIdx.y * 32;
    #pragma unroll
    for (int j = 0; j < 4; j++) {
        int idx = tid + j * 256;
        int r = idx >> 3, c4 = (idx & 7) * 4;
        *(float4*)&s[r][c4] = *(const float4*)(src + (size_t)(r0 + r) * D + c0 + c4);
    }
    __syncthreads();
    int w = tid >> 5, l = tid & 31;
    #pragma unroll
    for (int jj = 0; jj < 8; jj++) {
        int bi = w * 8 + jj;          // 0..63
        int nb = bi >> 2, kb = bi & 3;
        int nr = nb * 8 + (l >> 2), kc = kb * 8 + (l & 3);
        uint2 v;
        v.x = tf32r(s[nr][kc]);
        v.y = tf32r(s[nr][kc + 4]);
        size_t blk = (size_t)((c0 >> 3) + kb) * (R / 8) + (r0 >> 3) + nb;
        *(uint2*)(dst + blk * 64 + l * 2) = v;
    }
}

// ---------------- small vector kernels ----------------
__global__ void vecs_kernel(const float* __restrict__ Wq, const float* __restrict__ Wk,
                            const float* __restrict__ bq, const float* __restrict__ bk) {
    int gw   = (blockIdx.x * blockDim.x + threadIdx.x) >> 5;
    int lane = threadIdx.x & 31;
    float acc = 0.f;
    if (gw < D) {
        const float* row = Wq + (size_t)gw * D;
        for (int k = lane; k < D; k += 32) acc += row[k] * bk[k];
        #pragma unroll
        for (int o = 16; o > 0; o >>= 1) acc += __shfl_down_sync(0xffffffffu, acc, o);
        if (lane == 0) g_w1[gw] = acc;
    } else if (gw < 2*D) {
        const float* row = Wk + (size_t)(gw - D) * D;
        for (int k = lane; k < D; k += 32) acc += row[k] * bq[k];
        #pragma unroll
        for (int o = 16; o > 0; o >>= 1) acc += __shfl_down_sync(0xffffffffu, acc, o);
        if (lane == 0) g_w2[gw - D] = acc;
    } else if (gw == 2*D) {
        for (int k = lane; k < D; k += 32) acc += bq[k] * bk[k];
        #pragma unroll
        for (int o = 16; o > 0; o >>= 1) acc += __shfl_down_sync(0xffffffffu, acc, o);
        if (lane == 0) g_c0 = acc;
    }
}

__global__ void rows_kernel(const float* __restrict__ x, const float* __restrict__ Wo,
                            const float* __restrict__ bo) {
    int gw   = (blockIdx.x * blockDim.x + threadIdx.x) >> 5;
    int lane = threadIdx.x & 31;
    if (gw >= MROWS) return;
    const float* row = x + (size_t)gw * D;
    float ss = 0.f, pp = 0.f, qq = 0.f;
    for (int k = lane; k < D; k += 32) {
        float xv = row[k];
        ss += xv * Wo[k];
        pp += xv * g_w1[k];
        qq += xv * g_w2[k];
    }
    #pragma unroll
    for (int o = 16; o > 0; o >>= 1) {
        ss += __shfl_down_sync(0xffffffffu, ss, o);
        pp += __shfl_down_sync(0xffffffffu, pp, o);
        qq += __shfl_down_sync(0xffffffffu, qq, o);
    }
    if (lane == 0) {
        const float scale = 0.03125f;
        g_u[gw] = tanhf(ss + bo[0]);
        g_P[gw] = scale * (pp + g_c0);
        g_Q[gw] = scale * qq;
    }
}

// ---------------- pipelined tf32 GEMM on packed operands ----------------
// MODE 0: write C as B-packed tf32 (R_out = D).     [Wm']
// MODE 1: write C as A-packed tf32 (R_out = MROWS). [T]
// MODE 2: fused epilogue, row-major fp32 out, batched over blockIdx.z.
template<int MODE, int BMT>
__global__ void __launch_bounds__(THREADS, 1) mm_kernel(
    const uint32_t* __restrict__ Apk, const uint32_t* __restrict__ Bpk,
    void* __restrict__ Cout, int strideA, int strideB)
{
    constexpr int ATW = BMT * 16;         // A tile words (both k-halves)
    constexpr int BTW = BN * 16;          // 2048
    constexpr int STW = ATW + BTW;
    constexpr int WN_WARPS = (BMT == 256) ? 2 : 4;
    constexpr int TN = (BMT == 256) ? 8 : 4;

    extern __shared__ uint32_t sm[];
    const int tid = threadIdx.x, w = tid >> 5, lane = tid & 31;
    const int wm = (w / WN_WARPS) * 64;
    const int wn = (w % WN_WARPS) * (BN / WN_WARPS);
    const int zrow = (MODE == 2) ? blockIdx.z * NSEQ : 0;
    const int m0 = blockIdx.y * BMT, n0 = blockIdx.x * BN;

    const uint32_t* Abase = Apk + (size_t)((zrow + m0) >> 4) * 128;
    const uint32_t* Bbase = Bpk + (size_t)((zrow + n0) >> 3) * 64;
    uint32_t smbase = (uint32_t)__cvta_generic_to_shared(sm);

    float acc[4][TN][4] = {};

    auto issue = [&](int it, int st) {
        uint32_t sb = smbase + (uint32_t)(st * STW) * 4u;
        constexpr int ACH = ATW / 8;      // chunks per k-half of A
        #pragma unroll
        for (int j = 0; j < (2 * ACH) / THREADS; j++) {
            int idx = tid + j * THREADS;
            int kk = (idx >= ACH) ? 1 : 0;
            int off = idx - kk * ACH;
            cp16(sb + (uint32_t)(kk * (ATW/2) + off * 4) * 4u,
                 Abase + (size_t)(it * 2 + kk) * strideA + off * 4);
        }
        constexpr int BCH = BTW / 8;
        #pragma unroll
        for (int j = 0; j < (2 * BCH) / THREADS; j++) {
            int idx = tid + j * THREADS;
            int kk = (idx >= BCH) ? 1 : 0;
            int off = idx - kk * BCH;
            cp16(sb + (uint32_t)(ATW + kk * (BTW/2) + off * 4) * 4u,
                 Bbase + (size_t)(it * 2 + kk) * strideB + off * 4);
        }
        asm volatile("cp.async.commit_group;" ::: "memory");
    };

    issue(0, 0);
    issue(1, 1);

    const int mblk0 = wm >> 4, nblk0 = wn >> 3;
    for (int it = 0; it < NITER; it++) {
        int st = it % 3;
        asm volatile("cp.async.wait_group 1;" ::: "memory");
        __syncthreads();
        if (it + 2 < NITER) issue(it + 2, (it + 2) % 3);
        const uint32_t* base = sm + st * STW;
        #pragma unroll
        for (int ks = 0; ks < 2; ks++) {
            uint32_t afr[4][4], bfr[TN][2];
            #pragma unroll
            for (int tm = 0; tm < 4; tm++)
                *(uint4*)afr[tm] = *(const uint4*)&base[(ks * (BMT/16) + mblk0 + tm) * 128 + lane * 4];
            #pragma unroll
            for (int tn = 0; tn < TN; tn++)
                *(uint2*)bfr[tn] = *(const uint2*)&base[ATW + (ks * 16 + nblk0 + tn) * 64 + lane * 2];
            #pragma unroll
            for (int tm = 0; tm < 4; tm++)
                #pragma unroll
                for (int tn = 0; tn < TN; tn++)
                    mma_tf32(acc[tm][tn], afr[tm], bfr[tn]);
        }
        __syncthreads();
    }
    asm volatile("cp.async.wait_group 0;" ::: "memory");
    __syncthreads();

    // ---- epilogue ----
    if (MODE == 0) {
        uint32_t* Cd = (uint32_t*)Cout;
        #pragma unroll
        for (int tm = 0; tm < 4; tm++)
            #pragma unroll
            for (int tn = 0; tn < TN; tn++)
                #pragma unroll
                for (int e = 0; e < 4; e++) {
                    int r = m0 + wm + tm * 16 + (lane >> 2) + ((e >= 2) ? 8 : 0);
                    int c = n0 + wn + tn * 8 + (lane & 3) * 2 + (e & 1);
                    size_t wi = (size_t)(c >> 3) * ((D/8)*64) + (size_t)(r >> 3) * 64
                              + ((r & 7) * 4 + (c & 3)) * 2 + ((c >> 2) & 1);
                    Cd[wi] = tf32r(acc[tm][tn][e]);
                }
    } else if (MODE == 1) {
        uint32_t* Cd = (uint32_t*)Cout;
        #pragma unroll
        for (int tm = 0; tm < 4; tm++)
            #pragma unroll
            for (int tn = 0; tn < TN; tn++)
                #pragma unroll
                for (int e = 0; e < 4; e++) {
                    int r = m0 + wm + tm * 16 + (lane >> 2) + ((e >= 2) ? 8 : 0);
                    int c = n0 + wn + tn * 8 + (lane & 3) * 2 + (e & 1);
                    size_t wi = (size_t)(c >> 3) * ((MROWS/16)*128) + (size_t)(r >> 4) * 128
                              + ((r & 7) * 4 + (c & 3)) * 4 + ((c >> 2) & 1) * 2 + ((r >> 3) & 1);
                    Cd[wi] = tf32r(acc[tm][tn][e]);
                }
    } else {
        float* C = (float*)Cout;
        float* sQ = (float*)sm;
        float* sU = sQ + BN;
        int jg0 = blockIdx.z * NSEQ + n0;
        if (tid < BN) { sQ[tid] = g_Q[jg0 + tid]; sU[tid] = g_u[jg0 + tid]; }
        __syncthreads();
        const float scale = 0.03125f;
        size_t zr = (size_t)blockIdx.z * NSEQ;
        #pragma unroll
        for (int tm = 0; tm < 4; tm++) {
            int rloc0 = m0 + wm + tm * 16 + (lane >> 2);
            int rg0 = (int)zr + rloc0;
            float P0 = g_P[rg0],     u0 = g_u[rg0];
            float P1 = g_P[rg0 + 8], u1 = g_u[rg0 + 8];
            float* c0p = C + (zr + rloc0) * (size_t)NSEQ + n0;
            float* c1p = C + (zr + rloc0 + 8) * (size_t)NSEQ + n0;
            #pragma unroll
            for (int tn = 0; tn < TN; tn++) {
                int jl = wn + tn * 8 + (lane & 3) * 2;
                float qa = sQ[jl],   ua = sU[jl];
                float qb = sQ[jl+1], ub = sU[jl+1];
                float v00 = fmaf(scale, acc[tm][tn][0], P0 + qa)
                          + 5.f * __fdividef(ua - u0, fmaf(-u0, ua, 1.f));
                float v01 = fmaf(scale, acc[tm][tn][1], P0 + qb)
                          + 5.f * __fdividef(ub - u0, fmaf(-u0, ub, 1.f));
                float v10 = fmaf(scale, acc[tm][tn][2], P1 + qa)
                          + 5.f * __fdividef(ua - u1, fmaf(-u1, ua, 1.f));
                float v11 = fmaf(scale, acc[tm][tn][3], P1 + qb)
                          + 5.f * __fdividef(ub - u1, fmaf(-u1, ub, 1.f));
                *(float2*)(c0p + jl) = make_float2(v00, v01);
                *(float2*)(c1p + jl) = make_float2(v10, v11);
            }
        }
    }
}

// ---------------- launch ----------------
extern "C" void kernel_launch(void* const* d_in, const int* in_sizes, int n_in,
                              void* d_out, int out_size) {
    const float* x  = (const float*)d_in[0];
    const float* Wq = (const float*)d_in[1];
    const float* bq = (const float*)d_in[2];
    const float* Wk = (const float*)d_in[3];
    const float* bk = (const float*)d_in[4];
    const float* Wo = (const float*)d_in[5];
    const float* bo = (const float*)d_in[6];
    float* out = (float*)d_out;

    uint32_t *pxA, *pxB, *pWkA, *pWqB, *pWmB, *pTA;
    cudaGetSymbolAddress((void**)&pxA,  g_xA);
    cudaGetSymbolAddress((void**)&pxB,  g_xB);
    cudaGetSymbolAddress((void**)&pWkA, g_WkA);
    cudaGetSymbolAddress((void**)&pWqB, g_WqB);
    cudaGetSymbolAddress((void**)&pWmB, g_WmB);
    cudaGetSymbolAddress((void**)&pTA,  g_TA);

    const int SM256 = 3 * (256*16 + BN*16) * 4;   // 73728
    const int SM128 = 3 * (128*16 + BN*16) * 4;   // 49152
    cudaFuncSetAttribute(mm_kernel<0,128>, cudaFuncAttributeMaxDynamicSharedMemorySize, SM128);
    cudaFuncSetAttribute(mm_kernel<1,256>, cudaFuncAttributeMaxDynamicSharedMemorySize, SM256);
    cudaFuncSetAttribute(mm_kernel<2,256>, cudaFuncAttributeMaxDynamicSharedMemorySize, SM256);

    // bias precompute + operand packing
    vecs_kernel<<<257, 256>>>(Wq, Wk, bq, bk);
    rows_kernel<<<1024, 256>>>(x, Wo, bo);
    pack_A<<<dim3(MROWS/128, D/32), 256>>>(x,  pxA,  MROWS);
    pack_B<<<dim3(MROWS/128, D/32), 256>>>(x,  pxB,  MROWS);
    pack_A<<<dim3(D/128,     D/32), 256>>>(Wk, pWkA, D);
    pack_B<<<dim3(D/128,     D/32), 256>>>(Wq, pWqB, D);

    // Wm'[n,k] = Wm[k,n]: C0 = Wk @ Wq^T, written B-packed
    mm_kernel<0,128><<<dim3(D/BN, D/128), THREADS, SM128>>>(
        pWkA, pWqB, pWmB, (D/16)*128, (D/8)*64);
    // T = x @ Wm (via Wm' as B), written A-packed
    mm_kernel<1,256><<<dim3(D/BN, MROWS/256), THREADS, SM256>>>(
        pxA, pWmB, pTA, (MROWS/16)*128, (D/8)*64);
    // out[b,i,j] = scale*(T_b[i,:].x_b[j,:]) + P_i + Q_j + 5*tanh-identity
    mm_kernel<2,256><<<dim3(NSEQ/BN, NSEQ/256, BATCH), THREADS, SM256>>>(
        pTA, pxB, out, (MROWS/16)*128, (MROWS/8)*64);
}

// round 5
// speedup vs baseline: 3.8419x; 1.1053x over previous
#include <cuda_runtime.h>
#include <cstdint>
#include <math.h>

#define D      1024
#define BATCH  4
#define NSEQ   2048
#define MROWS  (BATCH*NSEQ)
#define BN     128
#define BK     32
#define NITER  (D/BK)        // 32
#define THREADS 256
#define STAGES 3

// ---------------- scratch (packed tf32 fragment-order operands) ----------------
__device__ uint32_t g_xA [MROWS*D];   // x packed as A-operand   (32MB)
__device__ uint32_t g_xB [MROWS*D];   // x packed as B-operand   (32MB)
__device__ uint32_t g_WkA[D*D];       // Wk packed as A          (4MB)
__device__ uint32_t g_WqB[D*D];       // Wq packed as B          (4MB)
__device__ uint32_t g_WmB[D*D];       // Wm' packed as B         (4MB)
__device__ uint32_t g_TA [MROWS*D];   // T packed as A           (32MB)
__device__ float g_w1[D];             // Wq @ bk
__device__ float g_w2[D];             // Wk @ bq
__device__ float g_P [MROWS];         // scale*(x@w1 + c0)
__device__ float g_Q [MROWS];         // scale*(x@w2)
__device__ float g_u [MROWS];         // tanh(x@Wo + bo)
__device__ float g_c0;                // bq . bk

__device__ __forceinline__ uint32_t tf32r(float x) {
    uint32_t o; asm("cvt.rna.tf32.f32 %0, %1;" : "=r"(o) : "f"(x));
    return o;
}
__device__ __forceinline__ void cp16(uint32_t saddr, const void* g) {
    asm volatile("cp.async.cg.shared.global [%0], [%1], 16;" :: "r"(saddr), "l"(g) : "memory");
}
__device__ __forceinline__ void mma_tf32(float c[4], const uint32_t a[4], const uint32_t b[2]) {
    asm volatile(
        "mma.sync.aligned.m16n8k8.row.col.f32.tf32.tf32.f32 "
        "{%0,%1,%2,%3}, {%4,%5,%6,%7}, {%8,%9}, {%0,%1,%2,%3};"
        : "+f"(c[0]), "+f"(c[1]), "+f"(c[2]), "+f"(c[3])
        : "r"(a[0]), "r"(a[1]), "r"(a[2]), "r"(a[3]), "r"(b[0]), "r"(b[1]));
}

// ---------------- pack helpers: row-major fp32 tile (128x32 in smem) -> fragment order
// A layout word: (k>>3)*(R/16)*128 + (m>>4)*128 + ((m&7)*4+(k&3))*4 + ((k>>2)&1)*2 + ((m>>3)&1)
// B layout word: (k>>3)*(R/8)*64   + (n>>3)*64  + ((n&7)*4+(k&3))*2 + ((k>>2)&1)
__device__ __forceinline__ void pack_tile_A(const float s[128][36], uint32_t* dst, int R,
                                            int r0, int c0, int w, int l) {
    #pragma unroll
    for (int jj = 0; jj < 4; jj++) {
        int bi = w + jj * 8;
        int mb = bi & 7, kb = bi >> 3;
        int mr = mb * 16 + (l >> 2), kc = kb * 8 + (l & 3);
        uint4 v;
        v.x = tf32r(s[mr][kc]);
        v.y = tf32r(s[mr + 8][kc]);
        v.z = tf32r(s[mr][kc + 4]);
        v.w = tf32r(s[mr + 8][kc + 4]);
        size_t blk = (size_t)((c0 >> 3) + kb) * (R / 16) + (r0 >> 4) + mb;
        *(uint4*)(dst + blk * 128 + l * 4) = v;
    }
}
__device__ __forceinline__ void pack_tile_B(const float s[128][36], uint32_t* dst, int R,
                                            int r0, int c0, int w, int l) {
    #pragma unroll
    for (int jj = 0; jj < 8; jj++) {
        int bi = w * 8 + jj;
        int nb = bi >> 2, kb = bi & 3;
        int nr = nb * 8 + (l >> 2), kc = kb * 8 + (l & 3);
        uint2 v;
        v.x = tf32r(s[nr][kc]);
        v.y = tf32r(s[nr][kc + 4]);
        size_t blk = (size_t)((c0 >> 3) + kb) * (R / 8) + (r0 >> 3) + nb;
        *(uint2*)(dst + blk * 64 + l * 2) = v;
    }
}
__device__ __forceinline__ void load_tile(const float* __restrict__ src, float s[128][36],
                                          int r0, int c0, int tid) {
    #pragma unroll
    for (int j = 0; j < 4; j++) {
        int idx = tid + j * 256;
        int r = idx >> 3, c4 = (idx & 7) * 4;
        *(float4*)&s[r][c4] = *(const float4*)(src + (size_t)(r0 + r) * D + c0 + c4);
    }
}

__global__ void pack_A(const float* __restrict__ src, uint32_t* __restrict__ dst, int R) {
    __shared__ float s[128][36];
    int tid = threadIdx.x, r0 = blockIdx.x * 128, c0 = blockIdx.y * 32;
    load_tile(src, s, r0, c0, tid);
    __syncthreads();
    pack_tile_A(s, dst, R, r0, c0, tid >> 5, tid & 31);
}
__global__ void pack_B(const float* __restrict__ src, uint32_t* __restrict__ dst, int R) {
    __shared__ float s[128][36];
    int tid = threadIdx.x, r0 = blockIdx.x * 128, c0 = blockIdx.y * 32;
    load_tile(src, s, r0, c0, tid);
    __syncthreads();
    pack_tile_B(s, dst, R, r0, c0, tid >> 5, tid & 31);
}
// fused: read x tile once, emit both layouts
__global__ void pack_x(const float* __restrict__ src, uint32_t* __restrict__ dstA,
                       uint32_t* __restrict__ dstB) {
    __shared__ float s[128][36];
    int tid = threadIdx.x, r0 = blockIdx.x * 128, c0 = blockIdx.y * 32;
    load_tile(src, s, r0, c0, tid);
    __syncthreads();
    pack_tile_A(s, dstA, MROWS, r0, c0, tid >> 5, tid & 31);
    pack_tile_B(s, dstB, MROWS, r0, c0, tid >> 5, tid & 31);
}

// ---------------- small vector kernels ----------------
__global__ void vecs_kernel(const float* __restrict__ Wq, const float* __restrict__ Wk,
                            const float* __restrict__ bq, const float* __restrict__ bk) {
    int gw   = (blockIdx.x * blockDim.x + threadIdx.x) >> 5;
    int lane = threadIdx.x & 31;
    float acc = 0.f;
    if (gw < D) {
        const float* row = Wq + (size_t)gw * D;
        for (int k = lane; k < D; k += 32) acc += row[k] * bk[k];
        #pragma unroll
        for (int o = 16; o > 0; o >>= 1) acc += __shfl_down_sync(0xffffffffu, acc, o);
        if (lane == 0) g_w1[gw] = acc;
    } else if (gw < 2*D) {
        const float* row = Wk + (size_t)(gw - D) * D;
        for (int k = lane; k < D; k += 32) acc += row[k] * bq[k];
        #pragma unroll
        for (int o = 16; o > 0; o >>= 1) acc += __shfl_down_sync(0xffffffffu, acc, o);
        if (lane == 0) g_w2[gw - D] = acc;
    } else if (gw == 2*D) {
        for (int k = lane; k < D; k += 32) acc += bq[k] * bk[k];
        #pragma unroll
        for (int o = 16; o > 0; o >>= 1) acc += __shfl_down_sync(0xffffffffu, acc, o);
        if (lane == 0) g_c0 = acc;
    }
}

__global__ void rows_kernel(const float* __restrict__ x, const float* __restrict__ Wo,
                            const float* __restrict__ bo) {
    int gw   = (blockIdx.x * blockDim.x + threadIdx.x) >> 5;
    int lane = threadIdx.x & 31;
    if (gw >= MROWS) return;
    const float* row = x + (size_t)gw * D;
    float ss = 0.f, pp = 0.f, qq = 0.f;
    for (int k = lane; k < D; k += 32) {
        float xv = row[k];
        ss += xv * Wo[k];
        pp += xv * g_w1[k];
        qq += xv * g_w2[k];
    }
    #pragma unroll
    for (int o = 16; o > 0; o >>= 1) {
        ss += __shfl_down_sync(0xffffffffu, ss, o);
        pp += __shfl_down_sync(0xffffffffu, pp, o);
        qq += __shfl_down_sync(0xffffffffu, qq, o);
    }
    if (lane == 0) {
        const float scale = 0.03125f;
        g_u[gw] = tanhf(ss + bo[0]);
        g_P[gw] = scale * (pp + g_c0);
        g_Q[gw] = scale * qq;
    }
}

// ---------------- pipelined tf32 GEMM on packed operands ----------------
// MODE 0: write C as B-packed tf32 (R_out = D).     [Wm']
// MODE 1: write C as A-packed tf32 (R_out = MROWS). [T]
// MODE 2: fused epilogue, row-major fp32 out, batched over blockIdx.z.
template<int MODE, int BMT>
__global__ void __launch_bounds__(THREADS, 1) mm_kernel(
    const uint32_t* __restrict__ Apk, const uint32_t* __restrict__ Bpk,
    void* __restrict__ Cout, int strideA, int strideB)
{
    constexpr int KSLAB_A = BMT * 8;          // words per k8-slab of A tile
    constexpr int KSLAB_B = (BN / 8) * 64;    // 1024
    constexpr int ATW = 4 * KSLAB_A;          // BK=32 -> 4 slabs
    constexpr int BTW = 4 * KSLAB_B;
    constexpr int STW = ATW + BTW;
    constexpr int WN_WARPS = (BMT == 256) ? 2 : 4;
    constexpr int TN = (BMT == 256) ? 8 : 4;

    extern __shared__ uint32_t sm[];
    const int tid = threadIdx.x, w = tid >> 5, lane = tid & 31;
    const int wm = (w / WN_WARPS) * 64;
    const int wn = (w % WN_WARPS) * (BN / WN_WARPS);
    const int zrow = (MODE == 2) ? blockIdx.z * NSEQ : 0;
    const int m0 = blockIdx.y * BMT, n0 = blockIdx.x * BN;

    const uint32_t* Abase = Apk + (size_t)((zrow + m0) >> 4) * 128;
    const uint32_t* Bbase = Bpk + (size_t)((zrow + n0) >> 3) * 64;
    uint32_t smbase = (uint32_t)__cvta_generic_to_shared(sm);

    float acc[4][TN][4] = {};

    auto issue = [&](int it, int st) {
        uint32_t sb = smbase + (uint32_t)(st * STW) * 4u;
        constexpr int ACH = KSLAB_A / 4;      // 16B chunks per A slab
        #pragma unroll
        for (int j = 0; j < (4 * ACH) / THREADS; j++) {
            int idx = tid + j * THREADS;
            int kk = idx / ACH, off = idx % ACH;
            cp16(sb + (uint32_t)(kk * KSLAB_A + off * 4) * 4u,
                 Abase + (size_t)(it * 4 + kk) * strideA + off * 4);
        }
        constexpr int BCH = KSLAB_B / 4;      // 256
        #pragma unroll
        for (int j = 0; j < (4 * BCH) / THREADS; j++) {
            int idx = tid + j * THREADS;
            int kk = idx / BCH, off = idx % BCH;
            cp16(sb + (uint32_t)(ATW + kk * KSLAB_B + off * 4) * 4u,
                 Bbase + (size_t)(it * 4 + kk) * strideB + off * 4);
        }
        asm volatile("cp.async.commit_group;" ::: "memory");
    };

    issue(0, 0);
    issue(1, 1);

    const int mblk0 = wm >> 4, nblk0 = wn >> 3;
    for (int it = 0; it < NITER; it++) {
        int st = it % STAGES;
        if (it < NITER - 1) asm volatile("cp.async.wait_group 1;" ::: "memory");
        else                asm volatile("cp.async.wait_group 0;" ::: "memory");
        __syncthreads();
        if (it + 2 < NITER) issue(it + 2, (it + 2) % STAGES);
        const uint32_t* base = sm + st * STW;
        #pragma unroll
        for (int ks = 0; ks < 4; ks++) {
            uint32_t afr[4][4], bfr[TN][2];
            #pragma unroll
            for (int tm = 0; tm < 4; tm++)
                *(uint4*)afr[tm] = *(const uint4*)&base[ks * KSLAB_A + (mblk0 + tm) * 128 + lane * 4];
            #pragma unroll
            for (int tn = 0; tn < TN; tn++)
                *(uint2*)bfr[tn] = *(const uint2*)&base[ATW + ks * KSLAB_B + (nblk0 + tn) * 64 + lane * 2];
            #pragma unroll
            for (int tm = 0; tm < 4; tm++)
                #pragma unroll
                for (int tn = 0; tn < TN; tn++)
                    mma_tf32(acc[tm][tn], afr[tm], bfr[tn]);
        }
        // NOTE: no trailing __syncthreads(): issue(it+2) targets stage (it-1)%3,
        // and every warp passed this iteration's top barrier only after finishing
        // compute on that stage.
    }

    // ---- epilogue ----
    if (MODE == 0) {
        uint32_t* Cd = (uint32_t*)Cout;
        #pragma unroll
        for (int tm = 0; tm < 4; tm++)
            #pragma unroll
            for (int tn = 0; tn < TN; tn++)
                #pragma unroll
                for (int e = 0; e < 4; e++) {
                    int r = m0 + wm + tm * 16 + (lane >> 2) + ((e >= 2) ? 8 : 0);
                    int c = n0 + wn + tn * 8 + (lane & 3) * 2 + (e & 1);
                    size_t wi = (size_t)(c >> 3) * ((D/8)*64) + (size_t)(r >> 3) * 64
                              + ((r & 7) * 4 + (c & 3)) * 2 + ((c >> 2) & 1);
                    Cd[wi] = tf32r(acc[tm][tn][e]);
                }
    } else if (MODE == 1) {
        uint32_t* Cd = (uint32_t*)Cout;
        #pragma unroll
        for (int tm = 0; tm < 4; tm++)
            #pragma unroll
            for (int tn = 0; tn < TN; tn++)
                #pragma unroll
                for (int e = 0; e < 4; e++) {
                    int r = m0 + wm + tm * 16 + (lane >> 2) + ((e >= 2) ? 8 : 0);
                    int c = n0 + wn + tn * 8 + (lane & 3) * 2 + (e & 1);
                    size_t wi = (size_t)(c >> 3) * ((MROWS/16)*128) + (size_t)(r >> 4) * 128
                              + ((r & 7) * 4 + (c & 3)) * 4 + ((c >> 2) & 1) * 2 + ((r >> 3) & 1);
                    Cd[wi] = tf32r(acc[tm][tn][e]);
                }
    } else {
        float* C = (float*)Cout;
        float* sQ = (float*)sm;
        float* sU = sQ + BN;
        int jg0 = blockIdx.z * NSEQ + n0;
        __syncthreads();
        if (tid < BN) { sQ[tid] = g_Q[jg0 + tid]; sU[tid] = g_u[jg0 + tid]; }
        __syncthreads();
        const float scale = 0.03125f;
        size_t zr = (size_t)blockIdx.z * NSEQ;
        #pragma unroll
        for (int tm = 0; tm < 4; tm++) {
            int rloc0 = m0 + wm + tm * 16 + (lane >> 2);
            int rg0 = (int)zr + rloc0;
            float P0 = g_P[rg0],     u0 = g_u[rg0];
            float P1 = g_P[rg0 + 8], u1 = g_u[rg0 + 8];
            float* c0p = C + (zr + rloc0) * (size_t)NSEQ + n0;
            float* c1p = C + (zr + rloc0 + 8) * (size_t)NSEQ + n0;
            #pragma unroll
            for (int tn = 0; tn < TN; tn++) {
                int jl = wn + tn * 8 + (lane & 3) * 2;
                float qa = sQ[jl],   ua = sU[jl];
                float qb = sQ[jl+1], ub = sU[jl+1];
                float v00 = fmaf(scale, acc[tm][tn][0], P0 + qa)
                          + 5.f * __fdividef(ua - u0, fmaf(-u0, ua, 1.f));
                float v01 = fmaf(scale, acc[tm][tn][1], P0 + qb)
                          + 5.f * __fdividef(ub - u0, fmaf(-u0, ub, 1.f));
                float v10 = fmaf(scale, acc[tm][tn][2], P1 + qa)
                          + 5.f * __fdividef(ua - u1, fmaf(-u1, ua, 1.f));
                float v11 = fmaf(scale, acc[tm][tn][3], P1 + qb)
                          + 5.f * __fdividef(ub - u1, fmaf(-u1, ub, 1.f));
                *(float2*)(c0p + jl) = make_float2(v00, v01);
                *(float2*)(c1p + jl) = make_float2(v10, v11);
            }
        }
    }
}

// ---------------- launch ----------------
extern "C" void kernel_launch(void* const* d_in, const int* in_sizes, int n_in,
                              void* d_out, int out_size) {
    const float* x  = (const float*)d_in[0];
    const float* Wq = (const float*)d_in[1];
    const float* bq = (const float*)d_in[2];
    const float* Wk = (const float*)d_in[3];
    const float* bk = (const float*)d_in[4];
    const float* Wo = (const float*)d_in[5];
    const float* bo = (const float*)d_in[6];
    float* out = (float*)d_out;

    uint32_t *pxA, *pxB, *pWkA, *pWqB, *pWmB, *pTA;
    cudaGetSymbolAddress((void**)&pxA,  g_xA);
    cudaGetSymbolAddress((void**)&pxB,  g_xB);
    cudaGetSymbolAddress((void**)&pWkA, g_WkA);
    cudaGetSymbolAddress((void**)&pWqB, g_WqB);
    cudaGetSymbolAddress((void**)&pWmB, g_WmB);
    cudaGetSymbolAddress((void**)&pTA,  g_TA);

    const int SM256 = STAGES * (256*32 + BN*32) * 4;   // 147456
    const int SM128 = STAGES * (128*32 + BN*32) * 4;   // 98304
    cudaFuncSetAttribute(mm_kernel<0,128>, cudaFuncAttributeMaxDynamicSharedMemorySize, SM128);
    cudaFuncSetAttribute(mm_kernel<1,256>, cudaFuncAttributeMaxDynamicSharedMemorySize, SM256);
    cudaFuncSetAttribute(mm_kernel<2,256>, cudaFuncAttributeMaxDynamicSharedMemorySize, SM256);

    // bias precompute + operand packing
    vecs_kernel<<<257, 256>>>(Wq, Wk, bq, bk);
    rows_kernel<<<1024, 256>>>(x, Wo, bo);
    pack_x<<<dim3(MROWS/128, D/32), 256>>>(x, pxA, pxB);
    pack_A<<<dim3(D/128,     D/32), 256>>>(Wk, pWkA, D);
    pack_B<<<dim3(D/128,     D/32), 256>>>(Wq, pWqB, D);

    // Wm'[n,k] = Wm[k,n]: C0 = Wk @ Wq^T, written B-packed
    mm_kernel<0,128><<<dim3(D/BN, D/128), THREADS, SM128>>>(
        pWkA, pWqB, pWmB, (D/16)*128, (D/8)*64);
    // T = x @ Wm (via Wm' as B), written A-packed
    mm_kernel<1,256><<<dim3(D/BN, MROWS/256), THREADS, SM256>>>(
        pxA, pWmB, pTA, (MROWS/16)*128, (D/8)*64);
    // out[b,i,j] = scale*(T_b[i,:].x_b[j,:]) + P_i + Q_j + 5*tanh-identity
    mm_kernel<2,256><<<dim3(NSEQ/BN, NSEQ/256, BATCH), THREADS, SM256>>>(
        pTA, pxB, out, (MROWS/16)*128, (MROWS/8)*64);
}

// round 6
// speedup vs baseline: 6.7456x; 1.7558x over previous
#include <cuda_runtime.h>
#include <cuda_fp16.h>
#include <cstdint>
#include <math.h>

#define D      1024
#define BATCH  4
#define NSEQ   2048
#define MROWS  (BATCH*NSEQ)
#define BN     128
#define BK     64
#define NITER  (D/BK)        // 16
#define THREADS 256
#define STAGES 3

// ---------------- scratch (fp16 fragment-order packed operands) ----------------
__device__ uint32_t g_xA [MROWS*D/2];   // x packed as A  (16MB)
__device__ uint32_t g_xB [MROWS*D/2];   // x packed as B  (16MB)
__device__ uint32_t g_WkA[D*D/2];       // Wk packed as A (2MB)
__device__ uint32_t g_WqB[D*D/2];       // Wq packed as B (2MB)
__device__ uint32_t g_WmB[D*D/2];       // Wm' packed as B(2MB)
__device__ uint32_t g_TA [MROWS*D/2];   // T packed as A  (16MB)
__device__ float g_w1[D];               // Wq @ bk
__device__ float g_w2[D];               // Wk @ bq
__device__ float g_P [MROWS];           // scale*(x@w1 + c0)
__device__ float g_Q [MROWS];           // scale*(x@w2)
__device__ float g_u [MROWS];           // tanh(x@Wo + bo)
__device__ float g_c0;                  // bq . bk

__device__ __forceinline__ uint32_t f2h2(float lo, float hi) {
    uint32_t r; asm("cvt.rn.f16x2.f32 %0, %1, %2;" : "=r"(r) : "f"(hi), "f"(lo));
    return r;
}
__device__ __forceinline__ void cp16(uint32_t saddr, const void* g) {
    asm volatile("cp.async.cg.shared.global [%0], [%1], 16;" :: "r"(saddr), "l"(g) : "memory");
}
__device__ __forceinline__ void mma_f16(float c[4], const uint32_t a[4], const uint32_t b[2]) {
    asm volatile(
        "mma.sync.aligned.m16n8k16.row.col.f32.f16.f16.f32 "
        "{%0,%1,%2,%3}, {%4,%5,%6,%7}, {%8,%9}, {%0,%1,%2,%3};"
        : "+f"(c[0]), "+f"(c[1]), "+f"(c[2]), "+f"(c[3])
        : "r"(a[0]), "r"(a[1]), "r"(a[2]), "r"(a[3]), "r"(b[0]), "r"(b[1]));
}

// ---------------- pack helpers: fp32 tile (128x32 smem) -> fp16 fragment order ------
// A word: (k>>4)*(R/16)*128 + (m>>4)*128 + ((m&7)*4 + ((k&7)>>1))*4
//         + ((k&8)>>3)*2 + ((m&8)>>3);  half = k&1 (low = even k)
// B word: (k>>4)*(R/8)*64 + (n>>3)*64 + ((n&7)*4 + ((k&7)>>1))*2 + ((k>>3)&1); half = k&1
__device__ __forceinline__ void pack_tile_A(const float s[128][36], uint32_t* dst, int R,
                                            int r0, int c0, int w, int l) {
    #pragma unroll
    for (int jj = 0; jj < 2; jj++) {
        int bi = w * 2 + jj;               // 0..15
        int mb = bi & 7, kb = bi >> 3;
        int mr = mb * 16 + (l >> 2);
        int kc = kb * 16 + (l & 3) * 2;
        uint4 v;
        v.x = f2h2(s[mr][kc],       s[mr][kc + 1]);
        v.y = f2h2(s[mr + 8][kc],   s[mr + 8][kc + 1]);
        v.z = f2h2(s[mr][kc + 8],   s[mr][kc + 9]);
        v.w = f2h2(s[mr + 8][kc + 8], s[mr + 8][kc + 9]);
        size_t blk = (size_t)((c0 >> 4) + kb) * (R / 16) + (r0 >> 4) + mb;
        *(uint4*)(dst + blk * 128 + l * 4) = v;
    }
}
__device__ __forceinline__ void pack_tile_B(const float s[128][36], uint32_t* dst, int R,
                                            int r0, int c0, int w, int l) {
    #pragma unroll
    for (int jj = 0; jj < 4; jj++) {
        int bi = w * 4 + jj;               // 0..31
        int nb = bi & 15, kb = bi >> 4;
        int nr = nb * 8 + (l >> 2);
        int kc = kb * 16 + (l & 3) * 2;
        uint2 v;
        v.x = f2h2(s[nr][kc],     s[nr][kc + 1]);
        v.y = f2h2(s[nr][kc + 8], s[nr][kc + 9]);
        size_t blk = (size_t)((c0 >> 4) + kb) * (R / 8) + (r0 >> 3) + nb;
        *(uint2*)(dst + blk * 64 + l * 2) = v;
    }
}
__device__ __forceinline__ void load_tile(const float* __restrict__ src, float s[128][36],
                                          int r0, int c0, int tid) {
    #pragma unroll
    for (int j = 0; j < 4; j++) {
        int idx = tid + j * 256;
        int r = idx >> 3, c4 = (idx & 7) * 4;
        *(float4*)&s[r][c4] = *(const float4*)(src + (size_t)(r0 + r) * D + c0 + c4);
    }
}

__global__ void pack_A(const float* __restrict__ src, uint32_t* __restrict__ dst, int R) {
    __shared__ float s[128][36];
    int tid = threadIdx.x, r0 = blockIdx.x * 128, c0 = blockIdx.y * 32;
    load_tile(src, s, r0, c0, tid);
    __syncthreads();
    pack_tile_A(s, dst, R, r0, c0, tid >> 5, tid & 31);
}
__global__ void pack_B(const float* __restrict__ src, uint32_t* __restrict__ dst, int R) {
    __shared__ float s[128][36];
    int tid = threadIdx.x, r0 = blockIdx.x * 128, c0 = blockIdx.y * 32;
    load_tile(src, s, r0, c0, tid);
    __syncthreads();
    pack_tile_B(s, dst, R, r0, c0, tid >> 5, tid & 31);
}
__global__ void pack_x(const float* __restrict__ src, uint32_t* __restrict__ dstA,
                       uint32_t* __restrict__ dstB) {
    __shared__ float s[128][36];
    int tid = threadIdx.x, r0 = blockIdx.x * 128, c0 = blockIdx.y * 32;
    load_tile(src, s, r0, c0, tid);
    __syncthreads();
    pack_tile_A(s, dstA, MROWS, r0, c0, tid >> 5, tid & 31);
    pack_tile_B(s, dstB, MROWS, r0, c0, tid >> 5, tid & 31);
}

// ---------------- small vector kernels ----------------
__global__ void vecs_kernel(const float* __restrict__ Wq, const float* __restrict__ Wk,
                            const float* __restrict__ bq, const float* __restrict__ bk) {
    int gw   = (blockIdx.x * blockDim.x + threadIdx.x) >> 5;
    int lane = threadIdx.x & 31;
    float acc = 0.f;
    if (gw < D) {
        const float* row = Wq + (size_t)gw * D;
        for (int k = lane; k < D; k += 32) acc += row[k] * bk[k];
        #pragma unroll
        for (int o = 16; o > 0; o >>= 1) acc += __shfl_down_sync(0xffffffffu, acc, o);
        if (lane == 0) g_w1[gw] = acc;
    } else if (gw < 2*D) {
        const float* row = Wk + (size_t)(gw - D) * D;
        for (int k = lane; k < D; k += 32) acc += row[k] * bq[k];
        #pragma unroll
        for (int o = 16; o > 0; o >>= 1) acc += __shfl_down_sync(0xffffffffu, acc, o);
        if (lane == 0) g_w2[gw - D] = acc;
    } else if (gw == 2*D) {
        for (int k = lane; k < D; k += 32) acc += bq[k] * bk[k];
        #pragma unroll
        for (int o = 16; o > 0; o >>= 1) acc += __shfl_down_sync(0xffffffffu, acc, o);
        if (lane == 0) g_c0 = acc;
    }
}

__global__ void rows_kernel(const float* __restrict__ x, const float* __restrict__ Wo,
                            const float* __restrict__ bo) {
    int gw   = (blockIdx.x * blockDim.x + threadIdx.x) >> 5;
    int lane = threadIdx.x & 31;
    if (gw >= MROWS) return;
    const float* row = x + (size_t)gw * D;
    float ss = 0.f, pp = 0.f, qq = 0.f;
    for (int k = lane; k < D; k += 32) {
        float xv = row[k];
        ss += xv * Wo[k];
        pp += xv * g_w1[k];
        qq += xv * g_w2[k];
    }
    #pragma unroll
    for (int o = 16; o > 0; o >>= 1) {
        ss += __shfl_down_sync(0xffffffffu, ss, o);
        pp += __shfl_down_sync(0xffffffffu, pp, o);
        qq += __shfl_down_sync(0xffffffffu, qq, o);
    }
    if (lane == 0) {
        const float scale = 0.03125f;
        g_u[gw] = tanhf(ss + bo[0]);
        g_P[gw] = scale * (pp + g_c0);
        g_Q[gw] = scale * qq;
    }
}

// ---------------- pipelined fp16 GEMM on packed operands ----------------
// MODE 0: write C as B-packed fp16 (R_out = D).     [Wm']
// MODE 1: write C as A-packed fp16 (R_out = MROWS). [T]
// MODE 2: fused epilogue, row-major fp32 out, batched over blockIdx.z.
template<int MODE, int BMT>
__global__ void __launch_bounds__(THREADS, 1) mm_kernel(
    const uint32_t* __restrict__ Apk, const uint32_t* __restrict__ Bpk,
    void* __restrict__ Cout, int strideA, int strideB)
{
    constexpr int KSLAB_A = (BMT / 16) * 128;   // words per k16-slab of A tile
    constexpr int KSLAB_B = (BN / 8) * 64;      // 1024
    constexpr int ATW = 4 * KSLAB_A;            // BK=64 -> 4 slabs
    constexpr int BTW = 4 * KSLAB_B;
    constexpr int STW = ATW + BTW;
    constexpr int WN_WARPS = (BMT == 256) ? 2 : 4;
    constexpr int TN = (BMT == 256) ? 8 : 4;

    extern __shared__ uint32_t sm[];
    const int tid = threadIdx.x, w = tid >> 5, lane = tid & 31;
    const int wm = (w / WN_WARPS) * 64;
    const int wn = (w % WN_WARPS) * (BN / WN_WARPS);
    const int zrow = (MODE == 2) ? blockIdx.z * NSEQ : 0;
    const int m0 = blockIdx.y * BMT, n0 = blockIdx.x * BN;

    const uint32_t* Abase = Apk + (size_t)((zrow + m0) >> 4) * 128;
    const uint32_t* Bbase = Bpk + (size_t)((zrow + n0) >> 3) * 64;
    uint32_t smbase = (uint32_t)__cvta_generic_to_shared(sm);

    float acc[4][TN][4] = {};

    auto issue = [&](int it, int st) {
        uint32_t sb = smbase + (uint32_t)(st * STW) * 4u;
        constexpr int ACH = KSLAB_A / 4;        // 16B chunks per A slab
        #pragma unroll
        for (int j = 0; j < (4 * ACH) / THREADS; j++) {
            int idx = tid + j * THREADS;
            int kk = idx / ACH, off = idx % ACH;
            cp16(sb + (uint32_t)(kk * KSLAB_A + off * 4) * 4u,
                 Abase + (size_t)(it * 4 + kk) * strideA + off * 4);
        }
        constexpr int BCH = KSLAB_B / 4;        // 256
        #pragma unroll
        for (int j = 0; j < (4 * BCH) / THREADS; j++) {
            int idx = tid + j * THREADS;
            int kk = idx / BCH, off = idx % BCH;
            cp16(sb + (uint32_t)(ATW + kk * KSLAB_B + off * 4) * 4u,
                 Bbase + (size_t)(it * 4 + kk) * strideB + off * 4);
        }
        asm volatile("cp.async.commit_group;" ::: "memory");
    };

    issue(0, 0);
    issue(1, 1);

    const int mblk0 = wm >> 4, nblk0 = wn >> 3;
    for (int it = 0; it < NITER; it++) {
        int st = it % STAGES;
        if (it < NITER - 1) asm volatile("cp.async.wait_group 1;" ::: "memory");
        else                asm volatile("cp.async.wait_group 0;" ::: "memory");
        __syncthreads();
        if (it + 2 < NITER) issue(it + 2, (it + 2) % STAGES);
        const uint32_t* base = sm + st * STW;
        #pragma unroll
        for (int ks = 0; ks < 4; ks++) {
            uint32_t afr[4][4], bfr[TN][2];
            #pragma unroll
            for (int tm = 0; tm < 4; tm++)
                *(uint4*)afr[tm] = *(const uint4*)&base[ks * KSLAB_A + (mblk0 + tm) * 128 + lane * 4];
            #pragma unroll
            for (int tn = 0; tn < TN; tn++)
                *(uint2*)bfr[tn] = *(const uint2*)&base[ATW + ks * KSLAB_B + (nblk0 + tn) * 64 + lane * 2];
            #pragma unroll
            for (int tm = 0; tm < 4; tm++)
                #pragma unroll
                for (int tn = 0; tn < TN; tn++)
                    mma_f16(acc[tm][tn], afr[tm], bfr[tn]);
        }
        // no trailing barrier: issue(it+2) targets stage (it-1)%3, already drained
        // by every warp having passed this iteration's top barrier.
    }

    // ---- epilogue ----
    if (MODE == 0) {
        // B-packed fp16 out, n = r, k = c
        uint32_t* Cd = (uint32_t*)Cout;
        #pragma unroll
        for (int tm = 0; tm < 4; tm++)
            #pragma unroll
            for (int tn = 0; tn < TN; tn++) {
                int r = m0 + wm + tm * 16 + (lane >> 2);
                int c = n0 + wn + tn * 8 + (lane & 3) * 2;
                uint32_t w0 = f2h2(acc[tm][tn][0], acc[tm][tn][1]);
                uint32_t w1 = f2h2(acc[tm][tn][2], acc[tm][tn][3]);
                size_t kslab = (size_t)(c >> 4) * (D / 8) * 64;
                int sub = ((c & 7) >> 1) * 2 + ((c >> 3) & 1);
                int r8 = r + 8;
                Cd[kslab + (size_t)(r  >> 3) * 64 + (r  & 7) * 8 + sub] = w0;
                Cd[kslab + (size_t)(r8 >> 3) * 64 + (r8 & 7) * 8 + sub] = w1;
            }
    } else if (MODE == 1) {
        // A-packed fp16 out, m = r, k = c
        uint32_t* Cd = (uint32_t*)Cout;
        #pragma unroll
        for (int tm = 0; tm < 4; tm++)
            #pragma unroll
            for (int tn = 0; tn < TN; tn++) {
                int r = m0 + wm + tm * 16 + (lane >> 2);
                int c = n0 + wn + tn * 8 + (lane & 3) * 2;
                uint32_t w0 = f2h2(acc[tm][tn][0], acc[tm][tn][1]);
                uint32_t w1 = f2h2(acc[tm][tn][2], acc[tm][tn][3]);
                size_t kslab = (size_t)(c >> 4) * (MROWS / 16) * 128;
                int sub = ((c & 7) >> 1) * 4 + ((c & 8) >> 3) * 2;
                int r8 = r + 8;
                Cd[kslab + (size_t)(r  >> 4) * 128 + (r  & 7) * 16 + sub + ((r  & 8) >> 3)] = w0;
                Cd[kslab + (size_t)(r8 >> 4) * 128 + (r8 & 7) * 16 + sub + ((r8 & 8) >> 3)] = w1;
            }
    } else {
        float* C = (float*)Cout;
        float* sQ = (float*)sm;
        float* sU = sQ + BN;
        int jg0 = blockIdx.z * NSEQ + n0;
        __syncthreads();
        if (tid < BN) { sQ[tid] = g_Q[jg0 + tid]; sU[tid] = g_u[jg0 + tid]; }
        __syncthreads();
        const float scale = 0.03125f;
        size_t zr = (size_t)blockIdx.z * NSEQ;
        #pragma unroll
        for (int tm = 0; tm < 4; tm++) {
            int rloc0 = m0 + wm + tm * 16 + (lane >> 2);
            int rg0 = (int)zr + rloc0;
            float P0 = g_P[rg0],     u0 = g_u[rg0];
            float P1 = g_P[rg0 + 8], u1 = g_u[rg0 + 8];
            float* c0p = C + (zr + rloc0) * (size_t)NSEQ + n0;
            float* c1p = C + (zr + rloc0 + 8) * (size_t)NSEQ + n0;
            #pragma unroll
            for (int tn = 0; tn < TN; tn++) {
                int jl = wn + tn * 8 + (lane & 3) * 2;
                float qa = sQ[jl],   ua = sU[jl];
                float qb = sQ[jl+1], ub = sU[jl+1];
                float v00 = fmaf(scale, acc[tm][tn][0], P0 + qa)
                          + 5.f * __fdividef(ua - u0, fmaf(-u0, ua, 1.f));
                float v01 = fmaf(scale, acc[tm][tn][1], P0 + qb)
                          + 5.f * __fdividef(ub - u0, fmaf(-u0, ub, 1.f));
                float v10 = fmaf(scale, acc[tm][tn][2], P1 + qa)
                          + 5.f * __fdividef(ua - u1, fmaf(-u1, ua, 1.f));
                float v11 = fmaf(scale, acc[tm][tn][3], P1 + qb)
                          + 5.f * __fdividef(ub - u1, fmaf(-u1, ub, 1.f));
                *(float2*)(c0p + jl) = make_float2(v00, v01);
                *(float2*)(c1p + jl) = make_float2(v10, v11);
            }
        }
    }
}

// ---------------- launch ----------------
extern "C" void kernel_launch(void* const* d_in, const int* in_sizes, int n_in,
                              void* d_out, int out_size) {
    const float* x  = (const float*)d_in[0];
    const float* Wq = (const float*)d_in[1];
    const float* bq = (const float*)d_in[2];
    const float* Wk = (const float*)d_in[3];
    const float* bk = (const float*)d_in[4];
    const float* Wo = (const float*)d_in[5];
    const float* bo = (const float*)d_in[6];
    float* out = (float*)d_out;

    uint32_t *pxA, *pxB, *pWkA, *pWqB, *pWmB, *pTA;
    cudaGetSymbolAddress((void**)&pxA,  g_xA);
    cudaGetSymbolAddress((void**)&pxB,  g_xB);
    cudaGetSymbolAddress((void**)&pWkA, g_WkA);
    cudaGetSymbolAddress((void**)&pWqB, g_WqB);
    cudaGetSymbolAddress((void**)&pWmB, g_WmB);
    cudaGetSymbolAddress((void**)&pTA,  g_TA);

    const int SM256 = STAGES * (4 * (256/16) * 128 + 4 * (BN/8) * 64) * 4;  // 147456
    const int SM128 = STAGES * (4 * (128/16) * 128 + 4 * (BN/8) * 64) * 4;  // 98304
    cudaFuncSetAttribute(mm_kernel<0,128>, cudaFuncAttributeMaxDynamicSharedMemorySize, SM128);
    cudaFuncSetAttribute(mm_kernel<1,256>, cudaFuncAttributeMaxDynamicSharedMemorySize, SM256);
    cudaFuncSetAttribute(mm_kernel<2,256>, cudaFuncAttributeMaxDynamicSharedMemorySize, SM256);

    // bias precompute + operand packing
    vecs_kernel<<<257, 256>>>(Wq, Wk, bq, bk);
    rows_kernel<<<1024, 256>>>(x, Wo, bo);
    pack_x<<<dim3(MROWS/128, D/32), 256>>>(x, pxA, pxB);
    pack_A<<<dim3(D/128,     D/32), 256>>>(Wk, pWkA, D);
    pack_B<<<dim3(D/128,     D/32), 256>>>(Wq, pWqB, D);

    // Wm'[n,k] = Wm[k,n]: C0 = Wk @ Wq^T, written B-packed
    mm_kernel<0,128><<<dim3(D/BN, D/128), THREADS, SM128>>>(
        pWkA, pWqB, pWmB, D*8, D*8);
    // T = x @ Wm (via Wm' as B), written A-packed
    mm_kernel<1,256><<<dim3(D/BN, MROWS/256), THREADS, SM256>>>(
        pxA, pWmB, pTA, MROWS*8, D*8);
    // out[b,i,j] = scale*(T_b[i,:].x_b[j,:]) + P_i + Q_j + 5*tanh-identity
    mm_kernel<2,256><<<dim3(NSEQ/BN, NSEQ/256, BATCH), THREADS, SM256>>>(
        pTA, pxB, out, MROWS*8, MROWS*8);
}

// round 7
// speedup vs baseline: 7.2958x; 1.0816x over previous
#include <cuda_runtime.h>
#include <cuda_fp16.h>
#include <cstdint>
#include <math.h>

#define D      1024
#define BATCH  4
#define NSEQ   2048
#define MROWS  (BATCH*NSEQ)
#define BN     128
#define BMT    128
#define BK     64
#define NITER  (D/BK)        // 16
#define THREADS 256
#define STAGES 3

// ---------------- scratch (fp16 fragment-order packed operands) ----------------
__device__ uint32_t g_xA [MROWS*D/2];   // x packed as A  (16MB)
__device__ uint32_t g_xB [MROWS*D/2];   // x packed as B  (16MB)
__device__ uint32_t g_WkA[D*D/2];       // Wk packed as A (2MB)
__device__ uint32_t g_WqB[D*D/2];       // Wq packed as B (2MB)
__device__ uint32_t g_WmB[D*D/2];       // Wm' packed as B(2MB)
__device__ uint32_t g_TA [MROWS*D/2];   // T packed as A  (16MB)
__device__ float g_w1[D];               // Wq @ bk
__device__ float g_w2[D];               // Wk @ bq
__device__ float g_P [MROWS];           // scale*(x@w1 + c0)
__device__ float g_Q [MROWS];           // scale*(x@w2)
__device__ float g_u [MROWS];           // tanh(x@Wo + bo)
__device__ float g_c0;                  // bq . bk

__device__ __forceinline__ uint32_t f2h2(float lo, float hi) {
    uint32_t r; asm("cvt.rn.f16x2.f32 %0, %1, %2;" : "=r"(r) : "f"(hi), "f"(lo));
    return r;
}
__device__ __forceinline__ void cp16(uint32_t saddr, const void* g) {
    asm volatile("cp.async.cg.shared.global [%0], [%1], 16;" :: "r"(saddr), "l"(g) : "memory");
}
__device__ __forceinline__ void mma_f16(float c[4], const uint32_t a[4], const uint32_t b[2]) {
    asm volatile(
        "mma.sync.aligned.m16n8k16.row.col.f32.f16.f16.f32 "
        "{%0,%1,%2,%3}, {%4,%5,%6,%7}, {%8,%9}, {%0,%1,%2,%3};"
        : "+f"(c[0]), "+f"(c[1]), "+f"(c[2]), "+f"(c[3])
        : "r"(a[0]), "r"(a[1]), "r"(a[2]), "r"(a[3]), "r"(b[0]), "r"(b[1]));
}

// ---------------- pack helpers: fp32 tile (128x32 smem) -> fp16 fragment order ------
__device__ __forceinline__ void pack_tile_A(const float s[128][36], uint32_t* dst, int R,
                                            int r0, int c0, int w, int l) {
    #pragma unroll
    for (int jj = 0; jj < 2; jj++) {
        int bi = w * 2 + jj;               // 0..15
        int mb = bi & 7, kb = bi >> 3;
        int mr = mb * 16 + (l >> 2);
        int kc = kb * 16 + (l & 3) * 2;
        uint4 v;
        v.x = f2h2(s[mr][kc],       s[mr][kc + 1]);
        v.y = f2h2(s[mr + 8][kc],   s[mr + 8][kc + 1]);
        v.z = f2h2(s[mr][kc + 8],   s[mr][kc + 9]);
        v.w = f2h2(s[mr + 8][kc + 8], s[mr + 8][kc + 9]);
        size_t blk = (size_t)((c0 >> 4) + kb) * (R / 16) + (r0 >> 4) + mb;
        *(uint4*)(dst + blk * 128 + l * 4) = v;
    }
}
__device__ __forceinline__ void pack_tile_B(const float s[128][36], uint32_t* dst, int R,
                                            int r0, int c0, int w, int l) {
    #pragma unroll
    for (int jj = 0; jj < 4; jj++) {
        int bi = w * 4 + jj;               // 0..31
        int nb = bi & 15, kb = bi >> 4;
        int nr = nb * 8 + (l >> 2);
        int kc = kb * 16 + (l & 3) * 2;
        uint2 v;
        v.x = f2h2(s[nr][kc],     s[nr][kc + 1]);
        v.y = f2h2(s[nr][kc + 8], s[nr][kc + 9]);
        size_t blk = (size_t)((c0 >> 4) + kb) * (R / 8) + (r0 >> 3) + nb;
        *(uint2*)(dst + blk * 64 + l * 2) = v;
    }
}
__device__ __forceinline__ void load_tile(const float* __restrict__ src, float s[128][36],
                                          int r0, int c0, int tid) {
    #pragma unroll
    for (int j = 0; j < 4; j++) {
        int idx = tid + j * 256;
        int r = idx >> 3, c4 = (idx & 7) * 4;
        *(float4*)&s[r][c4] = *(const float4*)(src + (size_t)(r0 + r) * D + c0 + c4);
    }
}

__global__ void pack_A(const float* __restrict__ src, uint32_t* __restrict__ dst, int R) {
    __shared__ float s[128][36];
    int tid = threadIdx.x, r0 = blockIdx.x * 128, c0 = blockIdx.y * 32;
    load_tile(src, s, r0, c0, tid);
    __syncthreads();
    pack_tile_A(s, dst, R, r0, c0, tid >> 5, tid & 31);
}
__global__ void pack_B(const float* __restrict__ src, uint32_t* __restrict__ dst, int R) {
    __shared__ float s[128][36];
    int tid = threadIdx.x, r0 = blockIdx.x * 128, c0 = blockIdx.y * 32;
    load_tile(src, s, r0, c0, tid);
    __syncthreads();
    pack_tile_B(s, dst, R, r0, c0, tid >> 5, tid & 31);
}
__global__ void pack_x(const float* __restrict__ src, uint32_t* __restrict__ dstA,
                       uint32_t* __restrict__ dstB) {
    __shared__ float s[128][36];
    int tid = threadIdx.x, r0 = blockIdx.x * 128, c0 = blockIdx.y * 32;
    load_tile(src, s, r0, c0, tid);
    __syncthreads();
    pack_tile_A(s, dstA, MROWS, r0, c0, tid >> 5, tid & 31);
    pack_tile_B(s, dstB, MROWS, r0, c0, tid >> 5, tid & 31);
}

// ---------------- small vector kernels ----------------
__global__ void vecs_kernel(const float* __restrict__ Wq, const float* __restrict__ Wk,
                            const float* __restrict__ bq, const float* __restrict__ bk) {
    int gw   = (blockIdx.x * blockDim.x + threadIdx.x) >> 5;
    int lane = threadIdx.x & 31;
    float acc = 0.f;
    if (gw < D) {
        const float* row = Wq + (size_t)gw * D;
        for (int k = lane; k < D; k += 32) acc += row[k] * bk[k];
        #pragma unroll
        for (int o = 16; o > 0; o >>= 1) acc += __shfl_down_sync(0xffffffffu, acc, o);
        if (lane == 0) g_w1[gw] = acc;
    } else if (gw < 2*D) {
        const float* row = Wk + (size_t)(gw - D) * D;
        for (int k = lane; k < D; k += 32) acc += row[k] * bq[k];
        #pragma unroll
        for (int o = 16; o > 0; o >>= 1) acc += __shfl_down_sync(0xffffffffu, acc, o);
        if (lane == 0) g_w2[gw - D] = acc;
    } else if (gw == 2*D) {
        for (int k = lane; k < D; k += 32) acc += bq[k] * bk[k];
        #pragma unroll
        for (int o = 16; o > 0; o >>= 1) acc += __shfl_down_sync(0xffffffffu, acc, o);
        if (lane == 0) g_c0 = acc;
    }
}

__global__ void rows_kernel(const float* __restrict__ x, const float* __restrict__ Wo,
                            const float* __restrict__ bo) {
    int gw   = (blockIdx.x * blockDim.x + threadIdx.x) >> 5;
    int lane = threadIdx.x & 31;
    if (gw >= MROWS) return;
    const float* row = x + (size_t)gw * D;
    float ss = 0.f, pp = 0.f, qq = 0.f;
    for (int k = lane; k < D; k += 32) {
        float xv = row[k];
        ss += xv * Wo[k];
        pp += xv * g_w1[k];
        qq += xv * g_w2[k];
    }
    #pragma unroll
    for (int o = 16; o > 0; o >>= 1) {
        ss += __shfl_down_sync(0xffffffffu, ss, o);
        pp += __shfl_down_sync(0xffffffffu, pp, o);
        qq += __shfl_down_sync(0xffffffffu, qq, o);
    }
    if (lane == 0) {
        const float scale = 0.03125f;
        g_u[gw] = tanhf(ss + bo[0]);
        g_P[gw] = scale * (pp + g_c0);
        g_Q[gw] = scale * qq;
    }
}

// ---------------- pipelined fp16 GEMM, 128x128 tile, 2 CTAs/SM ----------------
// MODE 0: write C as B-packed fp16 (R_out = D).     [Wm']
// MODE 1: write C as A-packed fp16 (R_out = MROWS). [T]
// MODE 2: fused epilogue, row-major fp32 out, batched over blockIdx.z.
template<int MODE>
__global__ void __launch_bounds__(THREADS, 2) mm_kernel(
    const uint32_t* __restrict__ Apk, const uint32_t* __restrict__ Bpk,
    void* __restrict__ Cout, int strideA, int strideB)
{
    constexpr int KSLAB_A = (BMT / 16) * 128;   // 1024 words per k16-slab
    constexpr int KSLAB_B = (BN / 8) * 64;      // 1024
    constexpr int ATW = 4 * KSLAB_A;            // BK=64 -> 4 slabs
    constexpr int BTW = 4 * KSLAB_B;
    constexpr int STW = ATW + BTW;              // 8192 words = 32KB/stage
    constexpr int TN = 4;                       // 2x4 warp grid, 64x32 warp tile

    extern __shared__ uint32_t sm[];
    const int tid = threadIdx.x, w = tid >> 5, lane = tid & 31;
    const int wm = (w >> 2) * 64;
    const int wn = (w & 3) * 32;
    const int zrow = (MODE == 2) ? blockIdx.z * NSEQ : 0;
    const int m0 = blockIdx.y * BMT, n0 = blockIdx.x * BN;

    const uint32_t* Abase = Apk + (size_t)((zrow + m0) >> 4) * 128;
    const uint32_t* Bbase = Bpk + (size_t)((zrow + n0) >> 3) * 64;
    uint32_t smbase = (uint32_t)__cvta_generic_to_shared(sm);

    float acc[4][TN][4] = {};

    auto issue = [&](int it, int st) {
        uint32_t sb = smbase + (uint32_t)(st * STW) * 4u;
        constexpr int ACH = KSLAB_A / 4;        // 256 16B-chunks per slab
        #pragma unroll
        for (int j = 0; j < (4 * ACH) / THREADS; j++) {
            int idx = tid + j * THREADS;
            int kk = idx / ACH, off = idx % ACH;
            cp16(sb + (uint32_t)(kk * KSLAB_A + off * 4) * 4u,
                 Abase + (size_t)(it * 4 + kk) * strideA + off * 4);
        }
        constexpr int BCH = KSLAB_B / 4;        // 256
        #pragma unroll
        for (int j = 0; j < (4 * BCH) / THREADS; j++) {
            int idx = tid + j * THREADS;
            int kk = idx / BCH, off = idx % BCH;
            cp16(sb + (uint32_t)(ATW + kk * KSLAB_B + off * 4) * 4u,
                 Bbase + (size_t)(it * 4 + kk) * strideB + off * 4);
        }
        asm volatile("cp.async.commit_group;" ::: "memory");
    };

    issue(0, 0);
    issue(1, 1);

    const int mblk0 = wm >> 4, nblk0 = wn >> 3;
    for (int it = 0; it < NITER; it++) {
        int st = it % STAGES;
        if (it < NITER - 1) asm volatile("cp.async.wait_group 1;" ::: "memory");
        else                asm volatile("cp.async.wait_group 0;" ::: "memory");
        __syncthreads();
        if (it + 2 < NITER) issue(it + 2, (it + 2) % STAGES);
        const uint32_t* base = sm + st * STW;
        #pragma unroll
        for (int ks = 0; ks < 4; ks++) {
            uint32_t afr[4][4], bfr[TN][2];
            #pragma unroll
            for (int tm = 0; tm < 4; tm++)
                *(uint4*)afr[tm] = *(const uint4*)&base[ks * KSLAB_A + (mblk0 + tm) * 128 + lane * 4];
            #pragma unroll
            for (int tn = 0; tn < TN; tn++)
                *(uint2*)bfr[tn] = *(const uint2*)&base[ATW + ks * KSLAB_B + (nblk0 + tn) * 64 + lane * 2];
            #pragma unroll
            for (int tm = 0; tm < 4; tm++)
                #pragma unroll
                for (int tn = 0; tn < TN; tn++)
                    mma_f16(acc[tm][tn], afr[tm], bfr[tn]);
        }
        // no trailing barrier: issue(it+2) targets stage (it-1)%3, already drained
        // by every warp having passed this iteration's top barrier.
    }

    // ---- epilogue ----
    if (MODE == 0) {
        // B-packed fp16 out, n = r, k = c
        uint32_t* Cd = (uint32_t*)Cout;
        #pragma unroll
        for (int tm = 0; tm < 4; tm++)
            #pragma unroll
            for (int tn = 0; tn < TN; tn++) {
                int r = m0 + wm + tm * 16 + (lane >> 2);
                int c = n0 + wn + tn * 8 + (lane & 3) * 2;
                uint32_t w0 = f2h2(acc[tm][tn][0], acc[tm][tn][1]);
                uint32_t w1 = f2h2(acc[tm][tn][2], acc[tm][tn][3]);
                size_t kslab = (size_t)(c >> 4) * (D / 8) * 64;
                int sub = ((c & 7) >> 1) * 2 + ((c >> 3) & 1);
                int r8 = r + 8;
                Cd[kslab + (size_t)(r  >> 3) * 64 + (r  & 7) * 8 + sub] = w0;
                Cd[kslab + (size_t)(r8 >> 3) * 64 + (r8 & 7) * 8 + sub] = w1;
            }
    } else if (MODE == 1) {
        // A-packed fp16 out, m = r, k = c
        uint32_t* Cd = (uint32_t*)Cout;
        #pragma unroll
        for (int tm = 0; tm < 4; tm++)
            #pragma unroll
            for (int tn = 0; tn < TN; tn++) {
                int r = m0 + wm + tm * 16 + (lane >> 2);
                int c = n0 + wn + tn * 8 + (lane & 3) * 2;
                uint32_t w0 = f2h2(acc[tm][tn][0], acc[tm][tn][1]);
                uint32_t w1 = f2h2(acc[tm][tn][2], acc[tm][tn][3]);
                size_t kslab = (size_t)(c >> 4) * (MROWS / 16) * 128;
                int sub = ((c & 7) >> 1) * 4 + ((c & 8) >> 3) * 2;
                int r8 = r + 8;
                Cd[kslab + (size_t)(r  >> 4) * 128 + (r  & 7) * 16 + sub + ((r  & 8) >> 3)] = w0;
                Cd[kslab + (size_t)(r8 >> 4) * 128 + (r8 & 7) * 16 + sub + ((r8 & 8) >> 3)] = w1;
            }
    } else {
        float* C = (float*)Cout;
        float* sQ = (float*)sm;
        float* sU = sQ + BN;
        int jg0 = blockIdx.z * NSEQ + n0;
        __syncthreads();
        if (tid < BN) { sQ[tid] = g_Q[jg0 + tid]; sU[tid] = g_u[jg0 + tid]; }
        __syncthreads();
        const float scale = 0.03125f;
        size_t zr = (size_t)blockIdx.z * NSEQ;
        #pragma unroll
        for (int tm = 0; tm < 4; tm++) {
            int rloc0 = m0 + wm + tm * 16 + (lane >> 2);
            int rg0 = (int)zr + rloc0;
            float P0 = g_P[rg0],     u0 = g_u[rg0];
            float P1 = g_P[rg0 + 8], u1 = g_u[rg0 + 8];
            float* c0p = C + (zr + rloc0) * (size_t)NSEQ + n0;
            float* c1p = C + (zr + rloc0 + 8) * (size_t)NSEQ + n0;
            #pragma unroll
            for (int tn = 0; tn < TN; tn++) {
                int jl = wn + tn * 8 + (lane & 3) * 2;
                float qa = sQ[jl],   ua = sU[jl];
                float qb = sQ[jl+1], ub = sU[jl+1];
                float v00 = fmaf(scale, acc[tm][tn][0], P0 + qa)
                          + 5.f * __fdividef(ua - u0, fmaf(-u0, ua, 1.f));
                float v01 = fmaf(scale, acc[tm][tn][1], P0 + qb)
                          + 5.f * __fdividef(ub - u0, fmaf(-u0, ub, 1.f));
                float v10 = fmaf(scale, acc[tm][tn][2], P1 + qa)
                          + 5.f * __fdividef(ua - u1, fmaf(-u1, ua, 1.f));
                float v11 = fmaf(scale, acc[tm][tn][3], P1 + qb)
                          + 5.f * __fdividef(ub - u1, fmaf(-u1, ub, 1.f));
                *(float2*)(c0p + jl) = make_float2(v00, v01);
                *(float2*)(c1p + jl) = make_float2(v10, v11);
            }
        }
    }
}

// ---------------- launch ----------------
extern "C" void kernel_launch(void* const* d_in, const int* in_sizes, int n_in,
                              void* d_out, int out_size) {
    const float* x  = (const float*)d_in[0];
    const float* Wq = (const float*)d_in[1];
    const float* bq = (const float*)d_in[2];
    const float* Wk = (const float*)d_in[3];
    const float* bk = (const float*)d_in[4];
    const float* Wo = (const float*)d_in[5];
    const float* bo = (const float*)d_in[6];
    float* out = (float*)d_out;

    uint32_t *pxA, *pxB, *pWkA, *pWqB, *pWmB, *pTA;
    cudaGetSymbolAddress((void**)&pxA,  g_xA);
    cudaGetSymbolAddress((void**)&pxB,  g_xB);
    cudaGetSymbolAddress((void**)&pWkA, g_WkA);
    cudaGetSymbolAddress((void**)&pWqB, g_WqB);
    cudaGetSymbolAddress((void**)&pWmB, g_WmB);
    cudaGetSymbolAddress((void**)&pTA,  g_TA);

    const int SMK = STAGES * (4 * (BMT/16) * 128 + 4 * (BN/8) * 64) * 4;  // 98304
    cudaFuncSetAttribute(mm_kernel<0>, cudaFuncAttributeMaxDynamicSharedMemorySize, SMK);
    cudaFuncSetAttribute(mm_kernel<1>, cudaFuncAttributeMaxDynamicSharedMemorySize, SMK);
    cudaFuncSetAttribute(mm_kernel<2>, cudaFuncAttributeMaxDynamicSharedMemorySize, SMK);

    // bias precompute + operand packing
    vecs_kernel<<<257, 256>>>(Wq, Wk, bq, bk);
    rows_kernel<<<1024, 256>>>(x, Wo, bo);
    pack_x<<<dim3(MROWS/128, D/32), 256>>>(x, pxA, pxB);
    pack_A<<<dim3(D/128,     D/32), 256>>>(Wk, pWkA, D);
    pack_B<<<dim3(D/128,     D/32), 256>>>(Wq, pWqB, D);

    // Wm'[n,k] = Wm[k,n]: C0 = Wk @ Wq^T, written B-packed
    mm_kernel<0><<<dim3(D/BN, D/BMT), THREADS, SMK>>>(
        pWkA, pWqB, pWmB, D*8, D*8);
    // T = x @ Wm (via Wm' as B), written A-packed
    mm_kernel<1><<<dim3(D/BN, MROWS/BMT), THREADS, SMK>>>(
        pxA, pWmB, pTA, MROWS*8, D*8);
    // out[b,i,j] = scale*(T_b[i,:].x_b[j,:]) + P_i + Q_j + 5*tanh-identity
    mm_kernel<2><<<dim3(NSEQ/BN, NSEQ/BMT, BATCH), THREADS, SMK>>>(
        pTA, pxB, out, MROWS*8, MROWS*8);
}

// round 8
// speedup vs baseline: 7.7043x; 1.0560x over previous
#include <cuda_runtime.h>
#include <cuda_fp16.h>
#include <cstdint>
#include <math.h>

#define D      1024
#define BATCH  4
#define NSEQ   2048
#define MROWS  (BATCH*NSEQ)
#define BN     128
#define BMT    128
#define BK     64
#define NITER  (D/BK)        // 16
#define THREADS 128
#define STAGES 3

// ---------------- scratch (fp16 fragment-order packed operands) ----------------
__device__ uint32_t g_xA [MROWS*D/2];   // x packed as A  (16MB)
__device__ uint32_t g_xB [MROWS*D/2];   // x packed as B  (16MB)
__device__ uint32_t g_WkA[D*D/2];       // Wk packed as A (2MB)
__device__ uint32_t g_WqB[D*D/2];       // Wq packed as B (2MB)
__device__ uint32_t g_WmB[D*D/2];       // Wm' packed as B(2MB)
__device__ uint32_t g_TA [MROWS*D/2];   // T packed as A  (16MB)
__device__ float g_w1[D];               // Wq @ bk
__device__ float g_w2[D];               // Wk @ bq
__device__ float g_P [MROWS];           // scale*(x@w1 + c0)
__device__ float g_Q [MROWS];           // scale*(x@w2)
__device__ float g_u [MROWS];           // tanh(x@Wo + bo)
__device__ float g_c0;                  // bq . bk

__device__ __forceinline__ uint32_t f2h2(float lo, float hi) {
    uint32_t r; asm("cvt.rn.f16x2.f32 %0, %1, %2;" : "=r"(r) : "f"(hi), "f"(lo));
    return r;
}
__device__ __forceinline__ void cp16(uint32_t saddr, const void* g) {
    asm volatile("cp.async.cg.shared.global [%0], [%1], 16;" :: "r"(saddr), "l"(g) : "memory");
}
__device__ __forceinline__ void mma_f16(float c[4], const uint32_t a[4], const uint32_t b[2]) {
    asm volatile(
        "mma.sync.aligned.m16n8k16.row.col.f32.f16.f16.f32 "
        "{%0,%1,%2,%3}, {%4,%5,%6,%7}, {%8,%9}, {%0,%1,%2,%3};"
        : "+f"(c[0]), "+f"(c[1]), "+f"(c[2]), "+f"(c[3])
        : "r"(a[0]), "r"(a[1]), "r"(a[2]), "r"(a[3]), "r"(b[0]), "r"(b[1]));
}

// ---------------- pack helpers: fp32 tile (128x32 smem) -> fp16 fragment order ------
__device__ __forceinline__ void pack_tile_A(const float s[128][36], uint32_t* dst, int R,
                                            int r0, int c0, int w, int l) {
    #pragma unroll
    for (int jj = 0; jj < 2; jj++) {
        int bi = w * 2 + jj;               // 0..15
        int mb = bi & 7, kb = bi >> 3;
        int mr = mb * 16 + (l >> 2);
        int kc = kb * 16 + (l & 3) * 2;
        uint4 v;
        v.x = f2h2(s[mr][kc],       s[mr][kc + 1]);
        v.y = f2h2(s[mr + 8][kc],   s[mr + 8][kc + 1]);
        v.z = f2h2(s[mr][kc + 8],   s[mr][kc + 9]);
        v.w = f2h2(s[mr + 8][kc + 8], s[mr + 8][kc + 9]);
        size_t blk = (size_t)((c0 >> 4) + kb) * (R / 16) + (r0 >> 4) + mb;
        *(uint4*)(dst + blk * 128 + l * 4) = v;
    }
}
__device__ __forceinline__ void pack_tile_B(const float s[128][36], uint32_t* dst, int R,
                                            int r0, int c0, int w, int l) {
    #pragma unroll
    for (int jj = 0; jj < 4; jj++) {
        int bi = w * 4 + jj;               // 0..31
        int nb = bi & 15, kb = bi >> 4;
        int nr = nb * 8 + (l >> 2);
        int kc = kb * 16 + (l & 3) * 2;
        uint2 v;
        v.x = f2h2(s[nr][kc],     s[nr][kc + 1]);
        v.y = f2h2(s[nr][kc + 8], s[nr][kc + 9]);
        size_t blk = (size_t)((c0 >> 4) + kb) * (R / 8) + (r0 >> 3) + nb;
        *(uint2*)(dst + blk * 64 + l * 2) = v;
    }
}
__device__ __forceinline__ void load_tile(const float* __restrict__ src, float s[128][36],
                                          int r0, int c0, int tid) {
    #pragma unroll
    for (int j = 0; j < 4; j++) {
        int idx = tid + j * 256;
        int r = idx >> 3, c4 = (idx & 7) * 4;
        *(float4*)&s[r][c4] = *(const float4*)(src + (size_t)(r0 + r) * D + c0 + c4);
    }
}

// fused: read x tile once, emit both layouts
__global__ void pack_x(const float* __restrict__ src, uint32_t* __restrict__ dstA,
                       uint32_t* __restrict__ dstB) {
    __shared__ float s[128][36];
    int tid = threadIdx.x, r0 = blockIdx.x * 128, c0 = blockIdx.y * 32;
    load_tile(src, s, r0, c0, tid);
    __syncthreads();
    pack_tile_A(s, dstA, MROWS, r0, c0, tid >> 5, tid & 31);
    pack_tile_B(s, dstB, MROWS, r0, c0, tid >> 5, tid & 31);
}
// weights: z=0 -> Wk as A, z=1 -> Wq as B (one launch)
__global__ void pack_w(const float* __restrict__ Wk, const float* __restrict__ Wq,
                       uint32_t* __restrict__ dstA, uint32_t* __restrict__ dstB) {
    __shared__ float s[128][36];
    int tid = threadIdx.x, r0 = blockIdx.x * 128, c0 = blockIdx.y * 32;
    if (blockIdx.z == 0) {
        load_tile(Wk, s, r0, c0, tid);
        __syncthreads();
        pack_tile_A(s, dstA, D, r0, c0, tid >> 5, tid & 31);
    } else {
        load_tile(Wq, s, r0, c0, tid);
        __syncthreads();
        pack_tile_B(s, dstB, D, r0, c0, tid >> 5, tid & 31);
    }
}

// ---------------- small vector kernels ----------------
__global__ void vecs_kernel(const float* __restrict__ Wq, const float* __restrict__ Wk,
                            const float* __restrict__ bq, const float* __restrict__ bk) {
    int gw   = (blockIdx.x * blockDim.x + threadIdx.x) >> 5;
    int lane = threadIdx.x & 31;
    float acc = 0.f;
    if (gw < D) {
        const float* row = Wq + (size_t)gw * D;
        for (int k = lane; k < D; k += 32) acc += row[k] * bk[k];
        #pragma unroll
        for (int o = 16; o > 0; o >>= 1) acc += __shfl_down_sync(0xffffffffu, acc, o);
        if (lane == 0) g_w1[gw] = acc;
    } else if (gw < 2*D) {
        const float* row = Wk + (size_t)(gw - D) * D;
        for (int k = lane; k < D; k += 32) acc += row[k] * bq[k];
        #pragma unroll
        for (int o = 16; o > 0; o >>= 1) acc += __shfl_down_sync(0xffffffffu, acc, o);
        if (lane == 0) g_w2[gw - D] = acc;
    } else if (gw == 2*D) {
        for (int k = lane; k < D; k += 32) acc += bq[k] * bk[k];
        #pragma unroll
        for (int o = 16; o > 0; o >>= 1) acc += __shfl_down_sync(0xffffffffu, acc, o);
        if (lane == 0) g_c0 = acc;
    }
}

__global__ void rows_kernel(const float* __restrict__ x, const float* __restrict__ Wo,
                            const float* __restrict__ bo) {
    int gw   = (blockIdx.x * blockDim.x + threadIdx.x) >> 5;
    int lane = threadIdx.x & 31;
    if (gw >= MROWS) return;
    const float* row = x + (size_t)gw * D;
    float ss = 0.f, pp = 0.f, qq = 0.f;
    for (int k = lane; k < D; k += 32) {
        float xv = row[k];
        ss += xv * Wo[k];
        pp += xv * g_w1[k];
        qq += xv * g_w2[k];
    }
    #pragma unroll
    for (int o = 16; o > 0; o >>= 1) {
        ss += __shfl_down_sync(0xffffffffu, ss, o);
        pp += __shfl_down_sync(0xffffffffu, pp, o);
        qq += __shfl_down_sync(0xffffffffu, qq, o);
    }
    if (lane == 0) {
        const float scale = 0.03125f;
        g_u[gw] = tanhf(ss + bo[0]);
        g_P[gw] = scale * (pp + g_c0);
        g_Q[gw] = scale * qq;
    }
}

// ---------------- fp16 GEMM, 128x128 tile, 4 warps (64x64 each), 2 CTAs/SM --------
// MODE 0: write C as B-packed fp16 (R_out = D).     [Wm']
// MODE 1: write C as A-packed fp16 (R_out = MROWS). [T]
// MODE 2: fused epilogue, row-major fp32 out, batched over blockIdx.z.
template<int MODE>
__global__ void __launch_bounds__(THREADS, 2) mm_kernel(
    const uint32_t* __restrict__ Apk, const uint32_t* __restrict__ Bpk,
    void* __restrict__ Cout, int strideA, int strideB)
{
    constexpr int KSLAB_A = (BMT / 16) * 128;   // 1024 words per k16-slab
    constexpr int KSLAB_B = (BN / 8) * 64;      // 1024
    constexpr int ATW = 4 * KSLAB_A;            // BK=64 -> 4 slabs = 16KB
    constexpr int BTW = 4 * KSLAB_B;
    constexpr int STW = ATW + BTW;              // 8192 words = 32KB/stage
    constexpr int TN = 8;                       // 2x2 warp grid, 64x64 warp tile

    extern __shared__ uint32_t sm[];
    const int tid = threadIdx.x, w = tid >> 5, lane = tid & 31;
    const int wm = (w >> 1) * 64;
    const int wn = (w & 1) * 64;
    const int zrow = (MODE == 2) ? blockIdx.z * NSEQ : 0;
    const int m0 = blockIdx.y * BMT, n0 = blockIdx.x * BN;

    const uint32_t* Abase = Apk + (size_t)((zrow + m0) >> 4) * 128;
    const uint32_t* Bbase = Bpk + (size_t)((zrow + n0) >> 3) * 64;
    uint32_t smbase = (uint32_t)__cvta_generic_to_shared(sm);

    float acc[4][TN][4] = {};

    auto issue = [&](int it, int st) {
        uint32_t sb = smbase + (uint32_t)(st * STW) * 4u;
        constexpr int ACH = KSLAB_A / 4;        // 256 16B-chunks per slab
        #pragma unroll
        for (int j = 0; j < (4 * ACH) / THREADS; j++) {
            int idx = tid + j * THREADS;
            int kk = idx / ACH, off = idx % ACH;
            cp16(sb + (uint32_t)(kk * KSLAB_A + off * 4) * 4u,
                 Abase + (size_t)(it * 4 + kk) * strideA + off * 4);
        }
        constexpr int BCH = KSLAB_B / 4;        // 256
        #pragma unroll
        for (int j = 0; j < (4 * BCH) / THREADS; j++) {
            int idx = tid + j * THREADS;
            int kk = idx / BCH, off = idx % BCH;
            cp16(sb + (uint32_t)(ATW + kk * KSLAB_B + off * 4) * 4u,
                 Bbase + (size_t)(it * 4 + kk) * strideB + off * 4);
        }
        asm volatile("cp.async.commit_group;" ::: "memory");
    };

    issue(0, 0);
    issue(1, 1);

    const int mblk0 = wm >> 4, nblk0 = wn >> 3;
    for (int it = 0; it < NITER; it++) {
        int st = it % STAGES;
        if (it < NITER - 1) asm volatile("cp.async.wait_group 1;" ::: "memory");
        else                asm volatile("cp.async.wait_group 0;" ::: "memory");
        __syncthreads();
        if (it + 2 < NITER) issue(it + 2, (it + 2) % STAGES);
        const uint32_t* base = sm + st * STW;
        #pragma unroll
        for (int ks = 0; ks < 4; ks++) {
            uint32_t afr[4][4], bfr[TN][2];
            #pragma unroll
            for (int tm = 0; tm < 4; tm++)
                *(uint4*)afr[tm] = *(const uint4*)&base[ks * KSLAB_A + (mblk0 + tm) * 128 + lane * 4];
            #pragma unroll
            for (int tn = 0; tn < TN; tn++)
                *(uint2*)bfr[tn] = *(const uint2*)&base[ATW + ks * KSLAB_B + (nblk0 + tn) * 64 + lane * 2];
            #pragma unroll
            for (int tm = 0; tm < 4; tm++)
                #pragma unroll
                for (int tn = 0; tn < TN; tn++)
                    mma_f16(acc[tm][tn], afr[tm], bfr[tn]);
        }
        // no trailing barrier: issue(it+2) targets stage (it-1)%3, already drained
        // by every warp having passed this iteration's top barrier.
    }

    // ---- epilogue ----
    if (MODE == 0) {
        // B-packed fp16 out, n = r, k = c
        uint32_t* Cd = (uint32_t*)Cout;
        #pragma unroll
        for (int tm = 0; tm < 4; tm++)
            #pragma unroll
            for (int tn = 0; tn < TN; tn++) {
                int r = m0 + wm + tm * 16 + (lane >> 2);
                int c = n0 + wn + tn * 8 + (lane & 3) * 2;
                uint32_t w0 = f2h2(acc[tm][tn][0], acc[tm][tn][1]);
                uint32_t w1 = f2h2(acc[tm][tn][2], acc[tm][tn][3]);
                size_t kslab = (size_t)(c >> 4) * (D / 8) * 64;
                int sub = ((c & 7) >> 1) * 2 + ((c >> 3) & 1);
                int r8 = r + 8;
                Cd[kslab + (size_t)(r  >> 3) * 64 + (r  & 7) * 8 + sub] = w0;
                Cd[kslab + (size_t)(r8 >> 3) * 64 + (r8 & 7) * 8 + sub] = w1;
            }
    } else if (MODE == 1) {
        // A-packed fp16 out, m = r, k = c
        uint32_t* Cd = (uint32_t*)Cout;
        #pragma unroll
        for (int tm = 0; tm < 4; tm++)
            #pragma unroll
            for (int tn = 0; tn < TN; tn++) {
                int r = m0 + wm + tm * 16 + (lane >> 2);
                int c = n0 + wn + tn * 8 + (lane & 3) * 2;
                uint32_t w0 = f2h2(acc[tm][tn][0], acc[tm][tn][1]);
                uint32_t w1 = f2h2(acc[tm][tn][2], acc[tm][tn][3]);
                size_t kslab = (size_t)(c >> 4) * (MROWS / 16) * 128;
                int sub = ((c & 7) >> 1) * 4 + ((c & 8) >> 3) * 2;
                int r8 = r + 8;
                Cd[kslab + (size_t)(r  >> 4) * 128 + (r  & 7) * 16 + sub + ((r  & 8) >> 3)] = w0;
                Cd[kslab + (size_t)(r8 >> 4) * 128 + (r8 & 7) * 16 + sub + ((r8 & 8) >> 3)] = w1;
            }
    } else {
        float* C = (float*)Cout;
        float* sQ = (float*)sm;
        float* sU = sQ + BN;
        int jg0 = blockIdx.z * NSEQ + n0;
        __syncthreads();
        if (tid < BN) { sQ[tid] = g_Q[jg0 + tid]; sU[tid] = g_u[jg0 + tid]; }
        __syncthreads();
        const float scale = 0.03125f;
        size_t zr = (size_t)blockIdx.z * NSEQ;
        #pragma unroll
        for (int tm = 0; tm < 4; tm++) {
            int rloc0 = m0 + wm + tm * 16 + (lane >> 2);
            int rg0 = (int)zr + rloc0;
            float P0 = g_P[rg0],     u0 = g_u[rg0];
            float P1 = g_P[rg0 + 8], u1 = g_u[rg0 + 8];
            float* c0p = C + (zr + rloc0) * (size_t)NSEQ + n0;
            float* c1p = C + (zr + rloc0 + 8) * (size_t)NSEQ + n0;
            #pragma unroll
            for (int tn = 0; tn < TN; tn++) {
                int jl = wn + tn * 8 + (lane & 3) * 2;
                float qa = sQ[jl],   ua = sU[jl];
                float qb = sQ[jl+1], ub = sU[jl+1];
                float v00 = fmaf(scale, acc[tm][tn][0], P0 + qa)
                          + 5.f * __fdividef(ua - u0, fmaf(-u0, ua, 1.f));
                float v01 = fmaf(scale, acc[tm][tn][1], P0 + qb)
                          + 5.f * __fdividef(ub - u0, fmaf(-u0, ub, 1.f));
                float v10 = fmaf(scale, acc[tm][tn][2], P1 + qa)
                          + 5.f * __fdividef(ua - u1, fmaf(-u1, ua, 1.f));
                float v11 = fmaf(scale, acc[tm][tn][3], P1 + qb)
                          + 5.f * __fdividef(ub - u1, fmaf(-u1, ub, 1.f));
                *(float2*)(c0p + jl) = make_float2(v00, v01);
                *(float2*)(c1p + jl) = make_float2(v10, v11);
            }
        }
    }
}

// ---------------- launch ----------------
extern "C" void kernel_launch(void* const* d_in, const int* in_sizes, int n_in,
                              void* d_out, int out_size) {
    const float* x  = (const float*)d_in[0];
    const float* Wq = (const float*)d_in[1];
    const float* bq = (const float*)d_in[2];
    const float* Wk = (const float*)d_in[3];
    const float* bk = (const float*)d_in[4];
    const float* Wo = (const float*)d_in[5];
    const float* bo = (const float*)d_in[6];
    float* out = (float*)d_out;

    uint32_t *pxA, *pxB, *pWkA, *pWqB, *pWmB, *pTA;
    cudaGetSymbolAddress((void**)&pxA,  g_xA);
    cudaGetSymbolAddress((void**)&pxB,  g_xB);
    cudaGetSymbolAddress((void**)&pWkA, g_WkA);
    cudaGetSymbolAddress((void**)&pWqB, g_WqB);
    cudaGetSymbolAddress((void**)&pWmB, g_WmB);
    cudaGetSymbolAddress((void**)&pTA,  g_TA);

    const int SMK = STAGES * (4 * (BMT/16) * 128 + 4 * (BN/8) * 64) * 4;  // 98304
    cudaFuncSetAttribute(mm_kernel<0>, cudaFuncAttributeMaxDynamicSharedMemorySize, SMK);
    cudaFuncSetAttribute(mm_kernel<1>, cudaFuncAttributeMaxDynamicSharedMemorySize, SMK);
    cudaFuncSetAttribute(mm_kernel<2>, cudaFuncAttributeMaxDynamicSharedMemorySize, SMK);

    // bias precompute + operand packing
    vecs_kernel<<<257, 256>>>(Wq, Wk, bq, bk);
    rows_kernel<<<1024, 256>>>(x, Wo, bo);
    pack_x<<<dim3(MROWS/128, D/32), 256>>>(x, pxA, pxB);
    pack_w<<<dim3(D/128, D/32, 2), 256>>>(Wk, Wq, pWkA, pWqB);

    // Wm'[n,k] = Wm[k,n]: C0 = Wk @ Wq^T, written B-packed
    mm_kernel<0><<<dim3(D/BN, D/BMT), THREADS, SMK>>>(
        pWkA, pWqB, pWmB, D*8, D*8);
    // T = x @ Wm (via Wm' as B), written A-packed
    mm_kernel<1><<<dim3(D/BN, MROWS/BMT), THREADS, SMK>>>(
        pxA, pWmB, pTA, MROWS*8, D*8);
    // out[b,i,j] = scale*(T_b[i,:].x_b[j,:]) + P_i + Q_j + 5*tanh-identity
    mm_kernel<2><<<dim3(NSEQ/BN, NSEQ/BMT, BATCH), THREADS, SMK>>>(
        pTA, pxB, out, MROWS*8, MROWS*8);
}

// round 9
// speedup vs baseline: 7.8949x; 1.0247x over previous
#include <cuda_runtime.h>
#include <cuda_fp16.h>
#include <cstdint>
#include <math.h>

#define D      1024
#define BATCH  4
#define NSEQ   2048
#define MROWS  (BATCH*NSEQ)
#define BN     128
#define BMT    128
#define BK     64
#define NITER  (D/BK)        // 16
#define THREADS 128
#define STAGES 3

// ---------------- scratch (fp16 fragment-order packed operands) ----------------
__device__ uint32_t g_xA [MROWS*D/2];   // x packed as A  (16MB)
__device__ uint32_t g_xB [MROWS*D/2];   // x packed as B  (16MB)
__device__ uint32_t g_WkA[D*D/2];       // Wk packed as A (2MB)
__device__ uint32_t g_WqB[D*D/2];       // Wq packed as B (2MB)
__device__ uint32_t g_WmB[D*D/2];       // Wm' packed as B(2MB)
__device__ uint32_t g_TA [MROWS*D/2];   // T packed as A  (16MB)
__device__ float g_w1[D];               // Wq @ bk
__device__ float g_w2[D];               // Wk @ bq
__device__ float g_P [MROWS];           // scale*(x@w1 + c0)
__device__ float g_Q [MROWS];           // scale*(x@w2)
__device__ float g_u [MROWS];           // tanh(x@Wo + bo)
__device__ float g_c0;                  // bq . bk

__device__ __forceinline__ uint32_t f2h2(float lo, float hi) {
    uint32_t r; asm("cvt.rn.f16x2.f32 %0, %1, %2;" : "=r"(r) : "f"(hi), "f"(lo));
    return r;
}
__device__ __forceinline__ void cp16(uint32_t saddr, const void* g) {
    asm volatile("cp.async.cg.shared.global [%0], [%1], 16;" :: "r"(saddr), "l"(g) : "memory");
}
__device__ __forceinline__ void mma_f16(float c[4], const uint32_t a[4], const uint32_t b[2]) {
    asm volatile(
        "mma.sync.aligned.m16n8k16.row.col.f32.f16.f16.f32 "
        "{%0,%1,%2,%3}, {%4,%5,%6,%7}, {%8,%9}, {%0,%1,%2,%3};"
        : "+f"(c[0]), "+f"(c[1]), "+f"(c[2]), "+f"(c[3])
        : "r"(a[0]), "r"(a[1]), "r"(a[2]), "r"(a[3]), "r"(b[0]), "r"(b[1]));
}

// ---------------- pack helpers: fp32 tile (128x32 smem) -> fp16 fragment order ------
__device__ __forceinline__ void pack_tile_A(const float s[128][36], uint32_t* dst, int R,
                                            int r0, int c0, int w, int l) {
    #pragma unroll
    for (int jj = 0; jj < 2; jj++) {
        int bi = w * 2 + jj;               // 0..15
        int mb = bi & 7, kb = bi >> 3;
        int mr = mb * 16 + (l >> 2);
        int kc = kb * 16 + (l & 3) * 2;
        uint4 v;
        v.x = f2h2(s[mr][kc],       s[mr][kc + 1]);
        v.y = f2h2(s[mr + 8][kc],   s[mr + 8][kc + 1]);
        v.z = f2h2(s[mr][kc + 8],   s[mr][kc + 9]);
        v.w = f2h2(s[mr + 8][kc + 8], s[mr + 8][kc + 9]);
        size_t blk = (size_t)((c0 >> 4) + kb) * (R / 16) + (r0 >> 4) + mb;
        *(uint4*)(dst + blk * 128 + l * 4) = v;
    }
}
__device__ __forceinline__ void pack_tile_B(const float s[128][36], uint32_t* dst, int R,
                                            int r0, int c0, int w, int l) {
    #pragma unroll
    for (int jj = 0; jj < 4; jj++) {
        int bi = w * 4 + jj;               // 0..31
        int nb = bi & 15, kb = bi >> 4;
        int nr = nb * 8 + (l >> 2);
        int kc = kb * 16 + (l & 3) * 2;
        uint2 v;
        v.x = f2h2(s[nr][kc],     s[nr][kc + 1]);
        v.y = f2h2(s[nr][kc + 8], s[nr][kc + 9]);
        size_t blk = (size_t)((c0 >> 4) + kb) * (R / 8) + (r0 >> 3) + nb;
        *(uint2*)(dst + blk * 64 + l * 2) = v;
    }
}
__device__ __forceinline__ void load_tile(const float* __restrict__ src, float s[128][36],
                                          int r0, int c0, int tid) {
    #pragma unroll
    for (int j = 0; j < 4; j++) {
        int idx = tid + j * 256;
        int r = idx >> 3, c4 = (idx & 7) * 4;
        *(float4*)&s[r][c4] = *(const float4*)(src + (size_t)(r0 + r) * D + c0 + c4);
    }
}

// fused: read x tile once, emit both layouts
__global__ void pack_x(const float* __restrict__ src, uint32_t* __restrict__ dstA,
                       uint32_t* __restrict__ dstB) {
    __shared__ float s[128][36];
    int tid = threadIdx.x, r0 = blockIdx.x * 128, c0 = blockIdx.y * 32;
    load_tile(src, s, r0, c0, tid);
    __syncthreads();
    pack_tile_A(s, dstA, MROWS, r0, c0, tid >> 5, tid & 31);
    pack_tile_B(s, dstB, MROWS, r0, c0, tid >> 5, tid & 31);
}
// weights: z=0 -> Wk as A, z=1 -> Wq as B (one launch)
__global__ void pack_w(const float* __restrict__ Wk, const float* __restrict__ Wq,
                       uint32_t* __restrict__ dstA, uint32_t* __restrict__ dstB) {
    __shared__ float s[128][36];
    int tid = threadIdx.x, r0 = blockIdx.x * 128, c0 = blockIdx.y * 32;
    if (blockIdx.z == 0) {
        load_tile(Wk, s, r0, c0, tid);
        __syncthreads();
        pack_tile_A(s, dstA, D, r0, c0, tid >> 5, tid & 31);
    } else {
        load_tile(Wq, s, r0, c0, tid);
        __syncthreads();
        pack_tile_B(s, dstB, D, r0, c0, tid >> 5, tid & 31);
    }
}

// ---------------- small vector kernels ----------------
__global__ void vecs_kernel(const float* __restrict__ Wq, const float* __restrict__ Wk,
                            const float* __restrict__ bq, const float* __restrict__ bk) {
    int gw   = (blockIdx.x * blockDim.x + threadIdx.x) >> 5;
    int lane = threadIdx.x & 31;
    float acc = 0.f;
    if (gw < D) {
        const float* row = Wq + (size_t)gw * D;
        for (int k = lane; k < D; k += 32) acc += row[k] * bk[k];
        #pragma unroll
        for (int o = 16; o > 0; o >>= 1) acc += __shfl_down_sync(0xffffffffu, acc, o);
        if (lane == 0) g_w1[gw] = acc;
    } else if (gw < 2*D) {
        const float* row = Wk + (size_t)(gw - D) * D;
        for (int k = lane; k < D; k += 32) acc += row[k] * bq[k];
        #pragma unroll
        for (int o = 16; o > 0; o >>= 1) acc += __shfl_down_sync(0xffffffffu, acc, o);
        if (lane == 0) g_w2[gw - D] = acc;
    } else if (gw == 2*D) {
        for (int k = lane; k < D; k += 32) acc += bq[k] * bk[k];
        #pragma unroll
        for (int o = 16; o > 0; o >>= 1) acc += __shfl_down_sync(0xffffffffu, acc, o);
        if (lane == 0) g_c0 = acc;
    }
}

__global__ void rows_kernel(const float* __restrict__ x, const float* __restrict__ Wo,
                            const float* __restrict__ bo) {
    int gw   = (blockIdx.x * blockDim.x + threadIdx.x) >> 5;
    int lane = threadIdx.x & 31;
    if (gw >= MROWS) return;
    const float* row = x + (size_t)gw * D;
    float ss = 0.f, pp = 0.f, qq = 0.f;
    for (int k = lane; k < D; k += 32) {
        float xv = row[k];
        ss += xv * Wo[k];
        pp += xv * g_w1[k];
        qq += xv * g_w2[k];
    }
    #pragma unroll
    for (int o = 16; o > 0; o >>= 1) {
        ss += __shfl_down_sync(0xffffffffu, ss, o);
        pp += __shfl_down_sync(0xffffffffu, pp, o);
        qq += __shfl_down_sync(0xffffffffu, qq, o);
    }
    if (lane == 0) {
        const float scale = 0.03125f;
        g_u[gw] = tanhf(ss + bo[0]);
        g_P[gw] = scale * (pp + g_c0);
        g_Q[gw] = scale * qq;
    }
}

// ---------------- fp16 GEMM, 128x128 tile, 4 warps (64x64 each), 2 CTAs/SM --------
// MODE 0: write C as B-packed fp16 (R_out = D).     [Wm']
// MODE 1: write C as A-packed fp16 (R_out = MROWS). [T]
// MODE 2: fused epilogue, row-major fp32 out, batched over blockIdx.z.
template<int MODE>
__global__ void __launch_bounds__(THREADS, 2) mm_kernel(
    const uint32_t* __restrict__ Apk, const uint32_t* __restrict__ Bpk,
    void* __restrict__ Cout, int strideA, int strideB)
{
    constexpr int KSLAB_A = (BMT / 16) * 128;   // 1024 words per k16-slab
    constexpr int KSLAB_B = (BN / 8) * 64;      // 1024
    constexpr int ATW = 4 * KSLAB_A;            // BK=64 -> 4 slabs = 16KB
    constexpr int BTW = 4 * KSLAB_B;
    constexpr int STW = ATW + BTW;              // 8192 words = 32KB/stage
    constexpr int TN = 8;                       // 2x2 warp grid, 64x64 warp tile

    extern __shared__ uint32_t sm[];
    const int tid = threadIdx.x, w = tid >> 5, lane = tid & 31;
    const int wm = (w >> 1) * 64;
    const int wn = (w & 1) * 64;
    const int zrow = (MODE == 2) ? blockIdx.z * NSEQ : 0;
    const int m0 = blockIdx.y * BMT, n0 = blockIdx.x * BN;

    const uint32_t* Abase = Apk + (size_t)((zrow + m0) >> 4) * 128;
    const uint32_t* Bbase = Bpk + (size_t)((zrow + n0) >> 3) * 64;
    uint32_t smbase = (uint32_t)__cvta_generic_to_shared(sm);

    float acc[4][TN][4] = {};

    auto issue = [&](int it, int st) {
        uint32_t sb = smbase + (uint32_t)(st * STW) * 4u;
        constexpr int ACH = KSLAB_A / 4;        // 256 16B-chunks per slab
        #pragma unroll
        for (int j = 0; j < (4 * ACH) / THREADS; j++) {
            int idx = tid + j * THREADS;
            int kk = idx / ACH, off = idx % ACH;
            cp16(sb + (uint32_t)(kk * KSLAB_A + off * 4) * 4u,
                 Abase + (size_t)(it * 4 + kk) * strideA + off * 4);
        }
        constexpr int BCH = KSLAB_B / 4;        // 256
        #pragma unroll
        for (int j = 0; j < (4 * BCH) / THREADS; j++) {
            int idx = tid + j * THREADS;
            int kk = idx / BCH, off = idx % BCH;
            cp16(sb + (uint32_t)(ATW + kk * KSLAB_B + off * 4) * 4u,
                 Bbase + (size_t)(it * 4 + kk) * strideB + off * 4);
        }
        asm volatile("cp.async.commit_group;" ::: "memory");
    };

    issue(0, 0);
    issue(1, 1);

    const int mblk0 = wm >> 4, nblk0 = wn >> 3;
    for (int it = 0; it < NITER; it++) {
        int st = it % STAGES;
        if (it < NITER - 1) asm volatile("cp.async.wait_group 1;" ::: "memory");
        else                asm volatile("cp.async.wait_group 0;" ::: "memory");
        __syncthreads();
        if (it + 2 < NITER) issue(it + 2, (it + 2) % STAGES);
        const uint32_t* base = sm + st * STW;
        #pragma unroll
        for (int ks = 0; ks < 4; ks++) {
            uint32_t afr[4][4], bfr[TN][2];
            #pragma unroll
            for (int tm = 0; tm < 4; tm++)
                *(uint4*)afr[tm] = *(const uint4*)&base[ks * KSLAB_A + (mblk0 + tm) * 128 + lane * 4];
            #pragma unroll
            for (int tn = 0; tn < TN; tn++)
                *(uint2*)bfr[tn] = *(const uint2*)&base[ATW + ks * KSLAB_B + (nblk0 + tn) * 64 + lane * 2];
            #pragma unroll
            for (int tm = 0; tm < 4; tm++)
                #pragma unroll
                for (int tn = 0; tn < TN; tn++)
                    mma_f16(acc[tm][tn], afr[tm], bfr[tn]);
        }
        // no trailing barrier: issue(it+2) targets stage (it-1)%3, already drained
        // by every warp having passed this iteration's top barrier.
    }

    // ---- epilogue ----
    if (MODE == 0) {
        // B-packed fp16 out, n = r, k = c
        uint32_t* Cd = (uint32_t*)Cout;
        #pragma unroll
        for (int tm = 0; tm < 4; tm++)
            #pragma unroll
            for (int tn = 0; tn < TN; tn++) {
                int r = m0 + wm + tm * 16 + (lane >> 2);
                int c = n0 + wn + tn * 8 + (lane & 3) * 2;
                uint32_t w0 = f2h2(acc[tm][tn][0], acc[tm][tn][1]);
                uint32_t w1 = f2h2(acc[tm][tn][2], acc[tm][tn][3]);
                size_t kslab = (size_t)(c >> 4) * (D / 8) * 64;
                int sub = ((c & 7) >> 1) * 2 + ((c >> 3) & 1);
                int r8 = r + 8;
                Cd[kslab + (size_t)(r  >> 3) * 64 + (r  & 7) * 8 + sub] = w0;
                Cd[kslab + (size_t)(r8 >> 3) * 64 + (r8 & 7) * 8 + sub] = w1;
            }
    } else if (MODE == 1) {
        // A-packed fp16 out, m = r, k = c
        uint32_t* Cd = (uint32_t*)Cout;
        #pragma unroll
        for (int tm = 0; tm < 4; tm++)
            #pragma unroll
            for (int tn = 0; tn < TN; tn++) {
                int r = m0 + wm + tm * 16 + (lane >> 2);
                int c = n0 + wn + tn * 8 + (lane & 3) * 2;
                uint32_t w0 = f2h2(acc[tm][tn][0], acc[tm][tn][1]);
                uint32_t w1 = f2h2(acc[tm][tn][2], acc[tm][tn][3]);
                size_t kslab = (size_t)(c >> 4) * (MROWS / 16) * 128;
                int sub = ((c & 7) >> 1) * 4 + ((c & 8) >> 3) * 2;
                int r8 = r + 8;
                Cd[kslab + (size_t)(r  >> 4) * 128 + (r  & 7) * 16 + sub + ((r  & 8) >> 3)] = w0;
                Cd[kslab + (size_t)(r8 >> 4) * 128 + (r8 & 7) * 16 + sub + ((r8 & 8) >> 3)] = w1;
            }
    } else {
        float* C = (float*)Cout;
        float* sQ = (float*)sm;
        float* sU = sQ + BN;
        int jg0 = blockIdx.z * NSEQ + n0;
        __syncthreads();
        if (tid < BN) { sQ[tid] = g_Q[jg0 + tid]; sU[tid] = g_u[jg0 + tid]; }
        __syncthreads();
        const float scale = 0.03125f;
        size_t zr = (size_t)blockIdx.z * NSEQ;
        #pragma unroll
        for (int tm = 0; tm < 4; tm++) {
            int rloc0 = m0 + wm + tm * 16 + (lane >> 2);
            int rg0 = (int)zr + rloc0;
            float P0 = g_P[rg0],     u0 = g_u[rg0];
            float P1 = g_P[rg0 + 8], u1 = g_u[rg0 + 8];
            float* c0p = C + (zr + rloc0) * (size_t)NSEQ + n0;
            float* c1p = C + (zr + rloc0 + 8) * (size_t)NSEQ + n0;
            #pragma unroll
            for (int tn = 0; tn < TN; tn++) {
                int jl = wn + tn * 8 + (lane & 3) * 2;
                float qa = sQ[jl],   ua = sU[jl];
                float qb = sQ[jl+1], ub = sU[jl+1];
                float v00 = fmaf(scale, acc[tm][tn][0], P0 + qa)
                          + 5.f * __fdividef(ua - u0, fmaf(-u0, ua, 1.f));
                float v01 = fmaf(scale, acc[tm][tn][1], P0 + qb)
                          + 5.f * __fdividef(ub - u0, fmaf(-u0, ub, 1.f));
                float v10 = fmaf(scale, acc[tm][tn][2], P1 + qa)
                          + 5.f * __fdividef(ua - u1, fmaf(-u1, ua, 1.f));
                float v11 = fmaf(scale, acc[tm][tn][3], P1 + qb)
                          + 5.f * __fdividef(ub - u1, fmaf(-u1, ub, 1.f));
                *(float2*)(c0p + jl) = make_float2(v00, v01);
                *(float2*)(c1p + jl) = make_float2(v10, v11);
            }
        }
    }
}

// ---------------- launch (multi-stream DAG, capture-safe fork/join) ----------------
extern "C" void kernel_launch(void* const* d_in, const int* in_sizes, int n_in,
                              void* d_out, int out_size) {
    const float* x  = (const float*)d_in[0];
    const float* Wq = (const float*)d_in[1];
    const float* bq = (const float*)d_in[2];
    const float* Wk = (const float*)d_in[3];
    const float* bk = (const float*)d_in[4];
    const float* Wo = (const float*)d_in[5];
    const float* bo = (const float*)d_in[6];
    float* out = (float*)d_out;

    uint32_t *pxA, *pxB, *pWkA, *pWqB, *pWmB, *pTA;
    cudaGetSymbolAddress((void**)&pxA,  g_xA);
    cudaGetSymbolAddress((void**)&pxB,  g_xB);
    cudaGetSymbolAddress((void**)&pWkA, g_WkA);
    cudaGetSymbolAddress((void**)&pWqB, g_WqB);
    cudaGetSymbolAddress((void**)&pWmB, g_WmB);
    cudaGetSymbolAddress((void**)&pTA,  g_TA);

    const int SMK = STAGES * (4 * (BMT/16) * 128 + 4 * (BN/8) * 64) * 4;  // 98304
    static bool attr_done = false;
    if (!attr_done) {
        cudaFuncSetAttribute(mm_kernel<0>, cudaFuncAttributeMaxDynamicSharedMemorySize, SMK);
        cudaFuncSetAttribute(mm_kernel<1>, cudaFuncAttributeMaxDynamicSharedMemorySize, SMK);
        cudaFuncSetAttribute(mm_kernel<2>, cudaFuncAttributeMaxDynamicSharedMemorySize, SMK);
        attr_done = true;
    }

    // side streams + events for capture-safe fork/join (created once, first call is
    // the uncaptured correctness run; every call records the identical DAG)
    static cudaStream_t s1 = nullptr, s2 = nullptr;
    static cudaEvent_t  eRoot = nullptr, eG0 = nullptr, ePX = nullptr;
    if (!s1) {
        cudaStreamCreateWithFlags(&s1, cudaStreamNonBlocking);
        cudaStreamCreateWithFlags(&s2, cudaStreamNonBlocking);
        cudaEventCreateWithFlags(&eRoot, cudaEventDisableTiming);
        cudaEventCreateWithFlags(&eG0,   cudaEventDisableTiming);
        cudaEventCreateWithFlags(&ePX,   cudaEventDisableTiming);
    }
    cudaStream_t s0 = 0;   // harness (capture) stream

    // fork
    cudaEventRecord(eRoot, s0);
    cudaStreamWaitEvent(s1, eRoot, 0);
    cudaStreamWaitEvent(s2, eRoot, 0);

    // branch 1: weight pack -> GEMM0 (Wm' = Wk @ Wq^T, B-packed)
    pack_w<<<dim3(D/128, D/32, 2), 256, 0, s1>>>(Wk, Wq, pWkA, pWqB);
    mm_kernel<0><<<dim3(D/BN, D/BMT), THREADS, SMK, s1>>>(pWkA, pWqB, pWmB, D*8, D*8);
    cudaEventRecord(eG0, s1);

    // branch 2: x pack (both layouts)
    pack_x<<<dim3(MROWS/128, D/32), 256, 0, s2>>>(x, pxA, pxB);
    cudaEventRecord(ePX, s2);

    // main: bias precompute (vecs -> rows)
    vecs_kernel<<<257, 256, 0, s0>>>(Wq, Wk, bq, bk);
    rows_kernel<<<1024, 256, 0, s0>>>(x, Wo, bo);

    // join: GEMM1 needs GEMM0 + pack_x(A); GEMM2 additionally needs rows (main-ordered)
    cudaStreamWaitEvent(s0, eG0, 0);
    cudaStreamWaitEvent(s0, ePX, 0);

    // T = x @ Wm (via Wm' as B), written A-packed
    mm_kernel<1><<<dim3(D/BN, MROWS/BMT), THREADS, SMK, s0>>>(pxA, pWmB, pTA, MROWS*8, D*8);
    // out[b,i,j] = scale*(T_b[i,:].x_b[j,:]) + P_i + Q_j + 5*tanh-identity
    mm_kernel<2><<<dim3(NSEQ/BN, NSEQ/BMT, BATCH), THREADS, SMK, s0>>>(
        pTA, pxB, out, MROWS*8, MROWS*8);
}

// round 10
// speedup vs baseline: 8.1716x; 1.0351x over previous
#include <cuda_runtime.h>
#include <cuda_fp16.h>
#include <cstdint>
#include <math.h>

#define D      1024
#define BATCH  4
#define NSEQ   2048
#define MROWS  (BATCH*NSEQ)
#define BN     128
#define BMT    128
#define BK     64
#define NITER  (D/BK)        // 16
#define NSLAB  (D/16)        // 64 k16-slabs total
#define THREADS 128
#define STAGES 3

// ---------------- scratch (fp16 fragment-order packed operands) ----------------
__device__ uint32_t g_xA [MROWS*D/2];   // x packed as A  (16MB)
__device__ uint32_t g_xB [MROWS*D/2];   // x packed as B  (16MB)
__device__ uint32_t g_WkA[D*D/2];       // Wk packed as A (2MB)
__device__ uint32_t g_WqB[D*D/2];       // Wq packed as B (2MB)
__device__ uint32_t g_WmB[D*D/2];       // Wm' packed as B(2MB)
__device__ uint32_t g_TA [MROWS*D/2];   // T packed as A  (16MB)
__device__ float g_w1[D];               // Wq @ bk
__device__ float g_w2[D];               // Wk @ bq
__device__ float g_P [MROWS];           // scale*(x@w1 + c0)
__device__ float g_Q [MROWS];           // scale*(x@w2)
__device__ float g_u [MROWS];           // tanh(x@Wo + bo)
__device__ float g_c0;                  // bq . bk

__device__ __forceinline__ uint32_t f2h2(float lo, float hi) {
    uint32_t r; asm("cvt.rn.f16x2.f32 %0, %1, %2;" : "=r"(r) : "f"(hi), "f"(lo));
    return r;
}
__device__ __forceinline__ void cp16(uint32_t saddr, const void* g) {
    asm volatile("cp.async.cg.shared.global [%0], [%1], 16;" :: "r"(saddr), "l"(g) : "memory");
}
__device__ __forceinline__ void mma_f16(float c[4], const uint32_t a[4], const uint32_t b[2]) {
    asm volatile(
        "mma.sync.aligned.m16n8k16.row.col.f32.f16.f16.f32 "
        "{%0,%1,%2,%3}, {%4,%5,%6,%7}, {%8,%9}, {%0,%1,%2,%3};"
        : "+f"(c[0]), "+f"(c[1]), "+f"(c[2]), "+f"(c[3])
        : "r"(a[0]), "r"(a[1]), "r"(a[2]), "r"(a[3]), "r"(b[0]), "r"(b[1]));
}

// ---------------- pack helpers: fp32 tile (128x32 smem) -> fp16 fragment order ------
__device__ __forceinline__ void pack_tile_A(const float s[128][36], uint32_t* dst, int R,
                                            int r0, int c0, int w, int l) {
    #pragma unroll
    for (int jj = 0; jj < 2; jj++) {
        int bi = w * 2 + jj;               // 0..15
        int mb = bi & 7, kb = bi >> 3;
        int mr = mb * 16 + (l >> 2);
        int kc = kb * 16 + (l & 3) * 2;
        uint4 v;
        v.x = f2h2(s[mr][kc],       s[mr][kc + 1]);
        v.y = f2h2(s[mr + 8][kc],   s[mr + 8][kc + 1]);
        v.z = f2h2(s[mr][kc + 8],   s[mr][kc + 9]);
        v.w = f2h2(s[mr + 8][kc + 8], s[mr + 8][kc + 9]);
        size_t blk = (size_t)((c0 >> 4) + kb) * (R / 16) + (r0 >> 4) + mb;
        *(uint4*)(dst + blk * 128 + l * 4) = v;
    }
}
__device__ __forceinline__ void pack_tile_B(const float s[128][36], uint32_t* dst, int R,
                                            int r0, int c0, int w, int l) {
    #pragma unroll
    for (int jj = 0; jj < 4; jj++) {
        int bi = w * 4 + jj;               // 0..31
        int nb = bi & 15, kb = bi >> 4;
        int nr = nb * 8 + (l >> 2);
        int kc = kb * 16 + (l & 3) * 2;
        uint2 v;
        v.x = f2h2(s[nr][kc],     s[nr][kc + 1]);
        v.y = f2h2(s[nr][kc + 8], s[nr][kc + 9]);
        size_t blk = (size_t)((c0 >> 4) + kb) * (R / 8) + (r0 >> 3) + nb;
        *(uint2*)(dst + blk * 64 + l * 2) = v;
    }
}
__device__ __forceinline__ void load_tile(const float* __restrict__ src, float s[128][36],
                                          int r0, int c0, int tid) {
    #pragma unroll
    for (int j = 0; j < 4; j++) {
        int idx = tid + j * 256;
        int r = idx >> 3, c4 = (idx & 7) * 4;
        *(float4*)&s[r][c4] = *(const float4*)(src + (size_t)(r0 + r) * D + c0 + c4);
    }
}

// fused: read x tile once, emit both layouts
__global__ void pack_x(const float* __restrict__ src, uint32_t* __restrict__ dstA,
                       uint32_t* __restrict__ dstB) {
    __shared__ float s[128][36];
    int tid = threadIdx.x, r0 = blockIdx.x * 128, c0 = blockIdx.y * 32;
    load_tile(src, s, r0, c0, tid);
    __syncthreads();
    pack_tile_A(s, dstA, MROWS, r0, c0, tid >> 5, tid & 31);
    pack_tile_B(s, dstB, MROWS, r0, c0, tid >> 5, tid & 31);
}
// weights: z=0 -> Wk as A, z=1 -> Wq as B (one launch)
__global__ void pack_w(const float* __restrict__ Wk, const float* __restrict__ Wq,
                       uint32_t* __restrict__ dstA, uint32_t* __restrict__ dstB) {
    __shared__ float s[128][36];
    int tid = threadIdx.x, r0 = blockIdx.x * 128, c0 = blockIdx.y * 32;
    if (blockIdx.z == 0) {
        load_tile(Wk, s, r0, c0, tid);
        __syncthreads();
        pack_tile_A(s, dstA, D, r0, c0, tid >> 5, tid & 31);
    } else {
        load_tile(Wq, s, r0, c0, tid);
        __syncthreads();
        pack_tile_B(s, dstB, D, r0, c0, tid >> 5, tid & 31);
    }
}

// ---------------- small vector kernels ----------------
__global__ void vecs_kernel(const float* __restrict__ Wq, const float* __restrict__ Wk,
                            const float* __restrict__ bq, const float* __restrict__ bk) {
    int gw   = (blockIdx.x * blockDim.x + threadIdx.x) >> 5;
    int lane = threadIdx.x & 31;
    float acc = 0.f;
    if (gw < D) {
        const float* row = Wq + (size_t)gw * D;
        for (int k = lane; k < D; k += 32) acc += row[k] * bk[k];
        #pragma unroll
        for (int o = 16; o > 0; o >>= 1) acc += __shfl_down_sync(0xffffffffu, acc, o);
        if (lane == 0) g_w1[gw] = acc;
    } else if (gw < 2*D) {
        const float* row = Wk + (size_t)(gw - D) * D;
        for (int k = lane; k < D; k += 32) acc += row[k] * bq[k];
        #pragma unroll
        for (int o = 16; o > 0; o >>= 1) acc += __shfl_down_sync(0xffffffffu, acc, o);
        if (lane == 0) g_w2[gw - D] = acc;
    } else if (gw == 2*D) {
        for (int k = lane; k < D; k += 32) acc += bq[k] * bk[k];
        #pragma unroll
        for (int o = 16; o > 0; o >>= 1) acc += __shfl_down_sync(0xffffffffu, acc, o);
        if (lane == 0) g_c0 = acc;
    }
}

__global__ void rows_kernel(const float* __restrict__ x, const float* __restrict__ Wo,
                            const float* __restrict__ bo) {
    int gw   = (blockIdx.x * blockDim.x + threadIdx.x) >> 5;
    int lane = threadIdx.x & 31;
    if (gw >= MROWS) return;
    const float* row = x + (size_t)gw * D;
    float ss = 0.f, pp = 0.f, qq = 0.f;
    for (int k = lane; k < D; k += 32) {
        float xv = row[k];
        ss += xv * Wo[k];
        pp += xv * g_w1[k];
        qq += xv * g_w2[k];
    }
    #pragma unroll
    for (int o = 16; o > 0; o >>= 1) {
        ss += __shfl_down_sync(0xffffffffu, ss, o);
        pp += __shfl_down_sync(0xffffffffu, pp, o);
        qq += __shfl_down_sync(0xffffffffu, qq, o);
    }
    if (lane == 0) {
        const float scale = 0.03125f;
        g_u[gw] = tanhf(ss + bo[0]);
        g_P[gw] = scale * (pp + g_c0);
        g_Q[gw] = scale * qq;
    }
}

// ---- fp16 GEMM: A via smem (cp.async, 3 stages), B via direct LDG from L2 with
//      distance-2 register prefetch (ring of 4 slots; slot = slab mod 4).
// MODE 0: write C as B-packed fp16 (R_out = D).     [Wm']
// MODE 1: write C as A-packed fp16 (R_out = MROWS). [T]
// MODE 2: fused epilogue, row-major fp32 out, batched over blockIdx.z.
template<int MODE>
__global__ void __launch_bounds__(THREADS, 2) mm_kernel(
    const uint32_t* __restrict__ Apk, const uint32_t* __restrict__ Bpk,
    void* __restrict__ Cout, int strideA, int strideB)
{
    constexpr int KSLAB_A = (BMT / 16) * 128;   // 1024 words per k16-slab
    constexpr int ATW = 4 * KSLAB_A;            // BK=64 -> 4 slabs = 16KB/stage
    constexpr int TN = 8;                       // 2x2 warp grid, 64x64 warp tile

    extern __shared__ uint32_t sm[];
    const int tid = threadIdx.x, w = tid >> 5, lane = tid & 31;
    const int wm = (w >> 1) * 64;
    const int wn = (w & 1) * 64;
    const int zrow = (MODE == 2) ? blockIdx.z * NSEQ : 0;
    const int m0 = blockIdx.y * BMT, n0 = blockIdx.x * BN;

    const uint32_t* Abase = Apk + (size_t)((zrow + m0) >> 4) * 128;
    const int mblk0 = wm >> 4, nblk0 = wn >> 3;
    // per-warp B fragment base: slab s, tile-n-block (nblk0+tn) -> Bf + s*strideB + tn*64
    const uint32_t* Bf = Bpk + (size_t)((zrow + n0) >> 3) * 64 + nblk0 * 64 + lane * 2;
    uint32_t smbase = (uint32_t)__cvta_generic_to_shared(sm);

    float acc[4][TN][4] = {};
    uint32_t bfr[4][TN][2];                      // B frag ring, slot = slab & 3

    auto ldB = [&](int slot, int slab) {
        const uint32_t* p = Bf + (size_t)slab * strideB;
        #pragma unroll
        for (int tn = 0; tn < TN; tn++)
            *(uint2*)bfr[slot][tn] = __ldg((const uint2*)(p + tn * 64));
    };

    auto issueA = [&](int it, int st) {
        uint32_t sb = smbase + (uint32_t)(st * ATW) * 4u;
        constexpr int ACH = KSLAB_A / 4;        // 256 16B-chunks per slab
        #pragma unroll
        for (int j = 0; j < (4 * ACH) / THREADS; j++) {
            int idx = tid + j * THREADS;
            int kk = idx / ACH, off = idx % ACH;
            cp16(sb + (uint32_t)(kk * KSLAB_A + off * 4) * 4u,
                 Abase + (size_t)(it * 4 + kk) * strideA + off * 4);
        }
        asm volatile("cp.async.commit_group;" ::: "memory");
    };

    issueA(0, 0);
    issueA(1, 1);
    ldB(0, 0);
    ldB(1, 1);

    for (int it = 0; it < NITER; it++) {
        int st = it % STAGES;
        if (it < NITER - 1) asm volatile("cp.async.wait_group 1;" ::: "memory");
        else                asm volatile("cp.async.wait_group 0;" ::: "memory");
        __syncthreads();
        if (it + 2 < NITER) issueA(it + 2, (it + 2) % STAGES);
        const uint32_t* base = sm + st * ATW;
        #pragma unroll
        for (int ks = 0; ks < 4; ks++) {
            // prefetch B for slab+2 into slot (ks+2)&3 (clamped; dup load past end)
            int pf = it * 4 + ks + 2;
            if (pf > NSLAB - 1) pf = NSLAB - 1;
            ldB((ks + 2) & 3, pf);
            uint32_t afr[4][4];
            #pragma unroll
            for (int tm = 0; tm < 4; tm++)
                *(uint4*)afr[tm] = *(const uint4*)&base[ks * KSLAB_A + (mblk0 + tm) * 128 + lane * 4];
            #pragma unroll
            for (int tm = 0; tm < 4; tm++)
                #pragma unroll
                for (int tn = 0; tn < TN; tn++)
                    mma_f16(acc[tm][tn], afr[tm], bfr[ks][tn]);
        }
        // no trailing barrier: issueA(it+2) targets stage (it-1)%3, already drained
        // by every warp having passed this iteration's top barrier.
    }

    // ---- epilogue ----
    if (MODE == 0) {
        // B-packed fp16 out, n = r, k = c
        uint32_t* Cd = (uint32_t*)Cout;
        #pragma unroll
        for (int tm = 0; tm < 4; tm++)
            #pragma unroll
            for (int tn = 0; tn < TN; tn++) {
                int r = m0 + wm + tm * 16 + (lane >> 2);
                int c = n0 + wn + tn * 8 + (lane & 3) * 2;
                uint32_t w0 = f2h2(acc[tm][tn][0], acc[tm][tn][1]);
                uint32_t w1 = f2h2(acc[tm][tn][2], acc[tm][tn][3]);
                size_t kslab = (size_t)(c >> 4) * (D / 8) * 64;
                int sub = ((c & 7) >> 1) * 2 + ((c >> 3) & 1);
                int r8 = r + 8;
                Cd[kslab + (size_t)(r  >> 3) * 64 + (r  & 7) * 8 + sub] = w0;
                Cd[kslab + (size_t)(r8 >> 3) * 64 + (r8 & 7) * 8 + sub] = w1;
            }
    } else if (MODE == 1) {
        // A-packed fp16 out, m = r, k = c
        uint32_t* Cd = (uint32_t*)Cout;
        #pragma unroll
        for (int tm = 0; tm < 4; tm++)
            #pragma unroll
            for (int tn = 0; tn < TN; tn++) {
                int r = m0 + wm + tm * 16 + (lane >> 2);
                int c = n0 + wn + tn * 8 + (lane & 3) * 2;
                uint32_t w0 = f2h2(acc[tm][tn][0], acc[tm][tn][1]);
                uint32_t w1 = f2h2(acc[tm][tn][2], acc[tm][tn][3]);
                size_t kslab = (size_t)(c >> 4) * (MROWS / 16) * 128;
                int sub = ((c & 7) >> 1) * 4 + ((c & 8) >> 3) * 2;
                int r8 = r + 8;
                Cd[kslab + (size_t)(r  >> 4) * 128 + (r  & 7) * 16 + sub + ((r  & 8) >> 3)] = w0;
                Cd[kslab + (size_t)(r8 >> 4) * 128 + (r8 & 7) * 16 + sub + ((r8 & 8) >> 3)] = w1;
            }
    } else {
        float* C = (float*)Cout;
        float* sQ = (float*)sm;
        float* sU = sQ + BN;
        int jg0 = blockIdx.z * NSEQ + n0;
        __syncthreads();
        if (tid < BN) { sQ[tid] = g_Q[jg0 + tid]; sU[tid] = g_u[jg0 + tid]; }
        __syncthreads();
        const float scale = 0.03125f;
        size_t zr = (size_t)blockIdx.z * NSEQ;
        #pragma unroll
        for (int tm = 0; tm < 4; tm++) {
            int rloc0 = m0 + wm + tm * 16 + (lane >> 2);
            int rg0 = (int)zr + rloc0;
            float P0 = g_P[rg0],     u0 = g_u[rg0];
            float P1 = g_P[rg0 + 8], u1 = g_u[rg0 + 8];
            float* c0p = C + (zr + rloc0) * (size_t)NSEQ + n0;
            float* c1p = C + (zr + rloc0 + 8) * (size_t)NSEQ + n0;
            #pragma unroll
            for (int tn = 0; tn < TN; tn++) {
                int jl = wn + tn * 8 + (lane & 3) * 2;
                float qa = sQ[jl],   ua = sU[jl];
                float qb = sQ[jl+1], ub = sU[jl+1];
                float v00 = fmaf(scale, acc[tm][tn][0], P0 + qa)
                          + 5.f * __fdividef(ua - u0, fmaf(-u0, ua, 1.f));
                float v01 = fmaf(scale, acc[tm][tn][1], P0 + qb)
                          + 5.f * __fdividef(ub - u0, fmaf(-u0, ub, 1.f));
                float v10 = fmaf(scale, acc[tm][tn][2], P1 + qa)
                          + 5.f * __fdividef(ua - u1, fmaf(-u1, ua, 1.f));
                float v11 = fmaf(scale, acc[tm][tn][3], P1 + qb)
                          + 5.f * __fdividef(ub - u1, fmaf(-u1, ub, 1.f));
                *(float2*)(c0p + jl) = make_float2(v00, v01);
                *(float2*)(c1p + jl) = make_float2(v10, v11);
            }
        }
    }
}

// ---------------- launch (multi-stream DAG, capture-safe fork/join) ----------------
extern "C" void kernel_launch(void* const* d_in, const int* in_sizes, int n_in,
                              void* d_out, int out_size) {
    const float* x  = (const float*)d_in[0];
    const float* Wq = (const float*)d_in[1];
    const float* bq = (const float*)d_in[2];
    const float* Wk = (const float*)d_in[3];
    const float* bk = (const float*)d_in[4];
    const float* Wo = (const float*)d_in[5];
    const float* bo = (const float*)d_in[6];
    float* out = (float*)d_out;

    uint32_t *pxA, *pxB, *pWkA, *pWqB, *pWmB, *pTA;
    cudaGetSymbolAddress((void**)&pxA,  g_xA);
    cudaGetSymbolAddress((void**)&pxB,  g_xB);
    cudaGetSymbolAddress((void**)&pWkA, g_WkA);
    cudaGetSymbolAddress((void**)&pWqB, g_WqB);
    cudaGetSymbolAddress((void**)&pWmB, g_WmB);
    cudaGetSymbolAddress((void**)&pTA,  g_TA);

    const int SMK = STAGES * 4 * (BMT/16) * 128 * 4;  // 49152 (A stages only)
    static bool attr_done = false;
    if (!attr_done) {
        cudaFuncSetAttribute(mm_kernel<0>, cudaFuncAttributeMaxDynamicSharedMemorySize, SMK);
        cudaFuncSetAttribute(mm_kernel<1>, cudaFuncAttributeMaxDynamicSharedMemorySize, SMK);
        cudaFuncSetAttribute(mm_kernel<2>, cudaFuncAttributeMaxDynamicSharedMemorySize, SMK);
        attr_done = true;
    }

    // side streams + events for capture-safe fork/join (created once, first call is
    // the uncaptured correctness run; every call records the identical DAG)
    static cudaStream_t s1 = nullptr, s2 = nullptr;
    static cudaEvent_t  eRoot = nullptr, eG0 = nullptr, ePX = nullptr;
    if (!s1) {
        cudaStreamCreateWithFlags(&s1, cudaStreamNonBlocking);
        cudaStreamCreateWithFlags(&s2, cudaStreamNonBlocking);
        cudaEventCreateWithFlags(&eRoot, cudaEventDisableTiming);
        cudaEventCreateWithFlags(&eG0,   cudaEventDisableTiming);
        cudaEventCreateWithFlags(&ePX,   cudaEventDisableTiming);
    }
    cudaStream_t s0 = 0;   // harness (capture) stream

    // fork
    cudaEventRecord(eRoot, s0);
    cudaStreamWaitEvent(s1, eRoot, 0);
    cudaStreamWaitEvent(s2, eRoot, 0);

    // branch 1: weight pack -> GEMM0 (Wm' = Wk @ Wq^T, B-packed)
    pack_w<<<dim3(D/128, D/32, 2), 256, 0, s1>>>(Wk, Wq, pWkA, pWqB);
    mm_kernel<0><<<dim3(D/BN, D/BMT), THREADS, SMK, s1>>>(pWkA, pWqB, pWmB, D*8, D*8);
    cudaEventRecord(eG0, s1);

    // branch 2: x pack (both layouts)
    pack_x<<<dim3(MROWS/128, D/32), 256, 0, s2>>>(x, pxA, pxB);
    cudaEventRecord(ePX, s2);

    // main: bias precompute (vecs -> rows)
    vecs_kernel<<<257, 256, 0, s0>>>(Wq, Wk, bq, bk);
    rows_kernel<<<1024, 256, 0, s0>>>(x, Wo, bo);

    // join: GEMM1 needs GEMM0 + pack_x(A); GEMM2 additionally needs rows (main-ordered)
    cudaStreamWaitEvent(s0, eG0, 0);
    cudaStreamWaitEvent(s0, ePX, 0);

    // T = x @ Wm (via Wm' as B), written A-packed
    mm_kernel<1><<<dim3(D/BN, MROWS/BMT), THREADS, SMK, s0>>>(pxA, pWmB, pTA, MROWS*8, D*8);
    // out[b,i,j] = scale*(T_b[i,:].x_b[j,:]) + P_i + Q_j + 5*tanh-identity
    mm_kernel<2><<<dim3(NSEQ/BN, NSEQ/BMT, BATCH), THREADS, SMK, s0>>>(
        pTA, pxB, out, MROWS*8, MROWS*8);
}